// round 6
// baseline (speedup 1.0000x reference)
#include <cuda_runtime.h>
#include <cstdint>

// ---------------------------------------------------------------------------
// Problem constants
//   B=128, T_V=64, T_A=128, E_V=1024, E_A=512, H=1024, EMB=512, C=512
//   IN=1024, VOCAB=20000
// Output = [logits(128*20000) | h_new(128*1024) | c_new(128*1024)]
// ---------------------------------------------------------------------------

// Scratch offsets (floats)
#define OFF_V2V     0u            // 8192*512
#define OFF_V2A     4194304u      // 16384*512
#define OFF_V1V     12582912u     // 128*512
#define OFF_V1A     12648448u     // 128*512
#define OFF_V1C     12713984u     // 128*512
#define OFF_CTXV    12779520u     // 128*1024
#define OFF_CTXA    12910592u     // 128*512
#define OFF_ALLCTX  12976128u     // 128*2*512
#define OFF_V2C     13107200u     // 256*512
#define OFF_X       13238272u     // 128*1024
#define OFF_GATES   13369344u     // 128*4096
#define OFF_H       13893632u     // 128*1024
// tf32-rounded operand copies
#define OFF_RENCV   14024704u     // 8388608
#define OFF_RENCA   22413312u     // 8388608
#define OFF_RH      30801920u     // 131072
#define OFF_RWVA2   30932992u     // 524288
#define OFF_RWAA2   31457280u     // 262144
#define OFF_RWHH    31719424u     // 4194304
#define OFF_RWVA1   35913728u     // 524288
#define OFF_RWAA1   36438016u     // 524288
#define OFF_RWCA1   36962304u     // 524288
#define SCRATCH_FLOATS 37486592u

__device__ float g_scratch[SCRATCH_FLOATS];
__device__ int g_bar[8];   // monotonic barrier counters (never reset; replay-safe)

__device__ __forceinline__ uint32_t f2tf(float f) {
    uint32_t u;
    asm("cvt.rna.tf32.f32 %0, %1;" : "=r"(u) : "f"(f));
    return u;
}

__device__ __forceinline__ void grid_bar(int i, int nblk) {
    __syncthreads();
    if (threadIdx.x == 0) {
        __threadfence();
        int old = atomicAdd(&g_bar[i], 1);
        int goal = (old / nblk + 1) * nblk;
        volatile int* p = &g_bar[i];
        while (*p < goal) { __nanosleep(64); }
        __threadfence();
    }
    __syncthreads();
}

// ---------------------------------------------------------------------------
// Pre-rounding pass: dst[i] = tf32_rna(src[i]) for 9 segments.
// ---------------------------------------------------------------------------
struct Seg { const float* s; float* d; unsigned n4; };
struct SegList { Seg seg[9]; unsigned tot4; };

__global__ void __launch_bounds__(256) preround(SegList L)
{
    for (unsigned u = blockIdx.x * 256u + threadIdx.x; u < L.tot4;
         u += gridDim.x * 256u) {
        unsigned r = u;
        int k = 0;
#pragma unroll
        for (int i = 0; i < 8; i++)
            if (r >= L.seg[k].n4) { r -= L.seg[k].n4; k++; }
        const float4 v = ((const float4*)L.seg[k].s)[r];
        uint4 o;
        o.x = f2tf(v.x); o.y = f2tf(v.y); o.z = f2tf(v.z); o.w = f2tf(v.w);
        ((uint4*)L.seg[k].d)[r] = o;
    }
}

// ---------------------------------------------------------------------------
// OLD TF32 core (register path + inline cvt) — used for chain + logits.
// Tile 64x64x32, 128 threads, warp tile 32x32.
// ---------------------------------------------------------------------------
__device__ __forceinline__ void gemm_core(
    const float* __restrict__ A, int lda,
    const float* __restrict__ B, int ldb,
    const float* __restrict__ bias,
    float* __restrict__ C, int ldc,
    int N, int K, int accum,
    int mBase, int nBase,
    uint32_t (*As)[36], uint32_t (*Bs)[36])
{
    const int tid  = threadIdx.x;
    const int lane = tid & 31;
    const int warp = tid >> 5;
    const int wm = warp >> 1;
    const int wn = warp & 1;
    const int lr = tid >> 3;
    const int lc = tid & 7;

    float acc[2][4][4];
#pragma unroll
    for (int i = 0; i < 2; i++)
#pragma unroll
        for (int j = 0; j < 4; j++)
#pragma unroll
            for (int k = 0; k < 4; k++) acc[i][j][k] = 0.f;

    const int nk = K >> 5;
    float4 pa[4], pb[4];

    {
        const float* Ap = A + (size_t)(mBase + lr) * lda + (lc << 2);
#pragma unroll
        for (int i = 0; i < 4; i++)
            pa[i] = *(const float4*)(Ap + (size_t)(i * 16) * lda);
#pragma unroll
        for (int i = 0; i < 4; i++) {
            const int nr = nBase + lr + i * 16;
            pb[i] = (nr < N) ? *(const float4*)(B + (size_t)nr * ldb + (lc << 2))
                             : make_float4(0.f, 0.f, 0.f, 0.f);
        }
    }
#pragma unroll
    for (int i = 0; i < 4; i++) {
        const int r = lr + (i << 4);
        uint4 v;
        v.x = f2tf(pa[i].x); v.y = f2tf(pa[i].y); v.z = f2tf(pa[i].z); v.w = f2tf(pa[i].w);
        *(uint4*)&As[r][lc << 2] = v;
        uint4 w;
        w.x = f2tf(pb[i].x); w.y = f2tf(pb[i].y); w.z = f2tf(pb[i].z); w.w = f2tf(pb[i].w);
        *(uint4*)&Bs[r][lc << 2] = w;
    }

    for (int kt = 0; kt < nk; kt++) {
        __syncthreads();
        const bool more = (kt + 1 < nk);
        if (more) {
            const int ko = (kt + 1) << 5;
            const float* Ap = A + (size_t)(mBase + lr) * lda + ko + (lc << 2);
#pragma unroll
            for (int i = 0; i < 4; i++)
                pa[i] = *(const float4*)(Ap + (size_t)(i * 16) * lda);
#pragma unroll
            for (int i = 0; i < 4; i++) {
                const int nr = nBase + lr + i * 16;
                pb[i] = (nr < N)
                    ? *(const float4*)(B + (size_t)nr * ldb + ko + (lc << 2))
                    : make_float4(0.f, 0.f, 0.f, 0.f);
            }
        }

#pragma unroll
        for (int kk = 0; kk < 32; kk += 8) {
            uint32_t a[2][4], b[4][2];
            const int c = kk + (lane & 3);
#pragma unroll
            for (int im = 0; im < 2; im++) {
                const int r = (wm << 5) + (im << 4) + (lane >> 2);
                a[im][0] = As[r][c];
                a[im][1] = As[r + 8][c];
                a[im][2] = As[r][c + 4];
                a[im][3] = As[r + 8][c + 4];
            }
#pragma unroll
            for (int jn = 0; jn < 4; jn++) {
                const int nr = (wn << 5) + (jn << 3) + (lane >> 2);
                b[jn][0] = Bs[nr][c];
                b[jn][1] = Bs[nr][c + 4];
            }
#pragma unroll
            for (int im = 0; im < 2; im++)
#pragma unroll
                for (int jn = 0; jn < 4; jn++)
                    asm volatile(
                        "mma.sync.aligned.m16n8k8.row.col.f32.tf32.tf32.f32 "
                        "{%0,%1,%2,%3}, {%4,%5,%6,%7}, {%8,%9}, {%0,%1,%2,%3};"
                        : "+f"(acc[im][jn][0]), "+f"(acc[im][jn][1]),
                          "+f"(acc[im][jn][2]), "+f"(acc[im][jn][3])
                        : "r"(a[im][0]), "r"(a[im][1]), "r"(a[im][2]), "r"(a[im][3]),
                          "r"(b[jn][0]), "r"(b[jn][1]));
        }

        __syncthreads();
        if (more) {
#pragma unroll
            for (int i = 0; i < 4; i++) {
                const int r = lr + (i << 4);
                uint4 v;
                v.x = f2tf(pa[i].x); v.y = f2tf(pa[i].y); v.z = f2tf(pa[i].z); v.w = f2tf(pa[i].w);
                *(uint4*)&As[r][lc << 2] = v;
                uint4 w;
                w.x = f2tf(pb[i].x); w.y = f2tf(pb[i].y); w.z = f2tf(pb[i].z); w.w = f2tf(pb[i].w);
                *(uint4*)&Bs[r][lc << 2] = w;
            }
        }
    }

#pragma unroll
    for (int im = 0; im < 2; im++) {
        const int m0 = mBase + (wm << 5) + (im << 4) + (lane >> 2);
#pragma unroll
        for (int jn = 0; jn < 4; jn++) {
            const int n0 = nBase + (wn << 5) + (jn << 3) + ((lane & 3) << 1);
#pragma unroll
            for (int half = 0; half < 2; half++) {
                const int m = m0 + half * 8;
                const float v0 = acc[im][jn][half * 2 + 0];
                const float v1 = acc[im][jn][half * 2 + 1];
                if (n0 < N) {
                    float xv = v0 + (bias ? bias[n0] : 0.f);
                    if (accum) C[(size_t)m * ldc + n0] += xv;
                    else       C[(size_t)m * ldc + n0]  = xv;
                }
                if (n0 + 1 < N) {
                    float xv = v1 + (bias ? bias[n0 + 1] : 0.f);
                    if (accum) C[(size_t)m * ldc + n0 + 1] += xv;
                    else       C[(size_t)m * ldc + n0 + 1]  = xv;
                }
            }
        }
    }
}

struct GemmGroup {
    const float* A; const float* B; const float* bias; float* C;
    int lda, ldb, ldc, N, K, accum, nbx, end;
};
struct GemmList { GemmGroup g[6]; int n; };

__global__ void __launch_bounds__(128) gemm_grouped(GemmList L)
{
    __shared__ uint32_t As[64][36];
    __shared__ uint32_t Bs[64][36];

    const int bid = blockIdx.x;
    int gi = 0;
#pragma unroll
    for (int i = 0; i < 6; i++)
        if (i < L.n && bid >= L.g[i].end) gi = i + 1;
    const GemmGroup& G = L.g[gi];
    const int start = gi ? L.g[gi - 1].end : 0;
    const int lb = bid - start;
    const int by = lb / G.nbx;
    const int bx = lb - by * G.nbx;

    gemm_core(G.A, G.lda, G.B, G.ldb, G.bias, G.C, G.ldc,
              G.N, G.K, G.accum, by << 6, bx << 6, As, Bs);
}

// ---------------------------------------------------------------------------
// NEW core: cp.async double-buffered + ldmatrix fragment loads.
// Operands MUST be pre-rounded tf32 (raw bit copies fed to HMMA).
// Tile 64x64x32, 128 threads, warp tile 32x32. M%64==0, N%64==0, K%32==0, K>=64.
// ---------------------------------------------------------------------------
__device__ __forceinline__ void cp16(uint32_t dst, const float* src) {
    asm volatile("cp.async.ca.shared.global [%0], [%1], 16;"
                 :: "r"(dst), "l"(src));
}
__device__ __forceinline__ void cp_commit() {
    asm volatile("cp.async.commit_group;");
}
__device__ __forceinline__ void ldsm4(uint32_t* r, uint32_t addr) {
    asm volatile("ldmatrix.sync.aligned.m8n8.x4.shared.b16 {%0,%1,%2,%3}, [%4];"
                 : "=r"(r[0]), "=r"(r[1]), "=r"(r[2]), "=r"(r[3]) : "r"(addr));
}

__global__ void __launch_bounds__(128) gemm_tcore(GemmList L)
{
    __shared__ uint32_t sA[2][64][36];
    __shared__ uint32_t sB[2][64][36];

    const int bid = blockIdx.x;
    int gi = 0;
#pragma unroll
    for (int i = 0; i < 6; i++)
        if (i < L.n && bid >= L.g[i].end) gi = i + 1;
    const GemmGroup& G = L.g[gi];
    const int start = gi ? L.g[gi - 1].end : 0;
    const int lb = bid - start;
    const int by = lb / G.nbx;
    const int bx = lb - by * G.nbx;
    const int mBase = by << 6, nBase = bx << 6;

    const float* __restrict__ A = G.A;
    const float* __restrict__ B = G.B;
    const int lda = G.lda, ldb = G.ldb;
    const int nk = G.K >> 5;

    const int tid  = threadIdx.x;
    const int lane = tid & 31;
    const int warp = tid >> 5;
    const int wm = warp >> 1;
    const int wn = warp & 1;
    const int lr = tid >> 3;
    const int lc = tid & 7;

    const uint32_t STAGE = 64u * 36u * 4u;   // bytes per stage

    // per-thread src/dst for the 4 A rows + 4 B rows it copies
    const float* aS[4]; const float* bS[4];
    uint32_t aD[4], bD[4];
#pragma unroll
    for (int i = 0; i < 4; i++) {
        aS[i] = A + (size_t)(mBase + lr + i * 16) * lda + (lc << 2);
        bS[i] = B + (size_t)(nBase + lr + i * 16) * ldb + (lc << 2);
        aD[i] = (uint32_t)__cvta_generic_to_shared(&sA[0][lr + i * 16][lc << 2]);
        bD[i] = (uint32_t)__cvta_generic_to_shared(&sB[0][lr + i * 16][lc << 2]);
    }

    // issue k-tile `kt` into stage buffer kt&1
    auto issue = [&](int kt) {
        const int ko = kt << 5;
        const uint32_t so = (kt & 1) ? STAGE : 0u;
#pragma unroll
        for (int i = 0; i < 4; i++) cp16(aD[i] + so, aS[i] + ko);
#pragma unroll
        for (int i = 0; i < 4; i++) cp16(bD[i] + so, bS[i] + ko);
        cp_commit();
    };

    float acc[2][4][4];
#pragma unroll
    for (int i = 0; i < 2; i++)
#pragma unroll
        for (int j = 0; j < 4; j++)
#pragma unroll
            for (int k = 0; k < 4; k++) acc[i][j][k] = 0.f;

    issue(0);
    if (nk > 1) issue(1);

    // precomputed ldmatrix lane addressing offsets
    const int l7 = lane & 7;
    const int q3 = (lane >> 3) & 1;   // quad bit 0
    const int q4 = (lane >> 4) & 1;   // quad bit 1
    const int aRow = (wm << 5) + l7 + (q3 << 3);   // + im*16
    const int aCol = (q4 << 2);                     // + kk
    const int bRow = (wn << 5) + l7 + (q4 << 3);   // + p*16
    const int bCol = (q3 << 2);                     // + kk

    for (int kt = 0; kt < nk; kt++) {
        if (kt < nk - 1) asm volatile("cp.async.wait_group 1;");
        else             asm volatile("cp.async.wait_group 0;");
        __syncthreads();

        const int s = kt & 1;
#pragma unroll
        for (int kk = 0; kk < 32; kk += 8) {
            uint32_t am[2][4], bm[2][4];
#pragma unroll
            for (int im = 0; im < 2; im++) {
                uint32_t addr = (uint32_t)__cvta_generic_to_shared(
                    &sA[s][aRow + (im << 4)][aCol + kk]);
                ldsm4(am[im], addr);
            }
#pragma unroll
            for (int p = 0; p < 2; p++) {
                uint32_t addr = (uint32_t)__cvta_generic_to_shared(
                    &sB[s][bRow + (p << 4)][bCol + kk]);
                ldsm4(bm[p], addr);
            }
#pragma unroll
            for (int im = 0; im < 2; im++)
#pragma unroll
                for (int jn = 0; jn < 4; jn++) {
                    const uint32_t b0 = bm[jn >> 1][(jn & 1) << 1];
                    const uint32_t b1 = bm[jn >> 1][((jn & 1) << 1) + 1];
                    asm volatile(
                        "mma.sync.aligned.m16n8k8.row.col.f32.tf32.tf32.f32 "
                        "{%0,%1,%2,%3}, {%4,%5,%6,%7}, {%8,%9}, {%0,%1,%2,%3};"
                        : "+f"(acc[im][jn][0]), "+f"(acc[im][jn][1]),
                          "+f"(acc[im][jn][2]), "+f"(acc[im][jn][3])
                        : "r"(am[im][0]), "r"(am[im][1]), "r"(am[im][2]), "r"(am[im][3]),
                          "r"(b0), "r"(b1));
                }
        }

        __syncthreads();
        if (kt + 2 < nk) issue(kt + 2);
    }

    // epilogue
    float* __restrict__ C = G.C;
    const int ldc = G.ldc;
#pragma unroll
    for (int im = 0; im < 2; im++) {
        const int m0 = mBase + (wm << 5) + (im << 4) + (lane >> 2);
#pragma unroll
        for (int jn = 0; jn < 4; jn++) {
            const int n0 = nBase + (wn << 5) + (jn << 3) + ((lane & 3) << 1);
#pragma unroll
            for (int half = 0; half < 2; half++) {
                const int m = m0 + half * 8;
                float v0 = acc[im][jn][half * 2 + 0];
                float v1 = acc[im][jn][half * 2 + 1];
                if (G.accum) {
                    C[(size_t)m * ldc + n0]     += v0;
                    C[(size_t)m * ldc + n0 + 1] += v1;
                } else {
                    C[(size_t)m * ldc + n0]     = v0;
                    C[(size_t)m * ldc + n0 + 1] = v1;
                }
            }
        }
    }
}

// ---------------------------------------------------------------------------
// Both Bahdanau attentions in one launch.
// ---------------------------------------------------------------------------
struct AttParams {
    const float* v1; const float* v2; const float* W3; const float* enc;
    float* ctx; int T, C, E;
};

__global__ void __launch_bounds__(256) attend_both(AttParams P0, AttParams P1)
{
    const AttParams P = (blockIdx.x >> 7) ? P1 : P0;
    const int b = blockIdx.x & 127;
    const int tid = threadIdx.x;
    const int warp = tid >> 5, lane = tid & 31;
    __shared__ float s_sc[128];
    __shared__ float s_inv;

    const int T = P.T, C = P.C, E = P.E;
    const float* v1b = P.v1 + (size_t)b * C;
    const float* v2b = P.v2 + (size_t)b * T * C;

    for (int t = warp; t < T; t += 8) {
        const float* row = v2b + (size_t)t * C;
        float acc = 0.f;
        for (int c = lane; c < C; c += 32)
            acc += tanhf(v1b[c] + row[c]) * P.W3[c];
#pragma unroll
        for (int o = 16; o; o >>= 1) acc += __shfl_xor_sync(0xffffffffu, acc, o);
        if (lane == 0) s_sc[t] = acc;
    }
    __syncthreads();

    if (tid == 0) {
        float m = -1e30f;
        for (int t = 0; t < T; t++) m = fmaxf(m, s_sc[t]);
        float s = 0.f;
        for (int t = 0; t < T; t++) { float e = expf(s_sc[t] - m); s_sc[t] = e; s += e; }
        s_inv = 1.f / s;
    }
    __syncthreads();
    const float inv = s_inv;

    const float* encb = P.enc + (size_t)b * T * E;
    for (int e = tid; e < E; e += 256) {
        float acc = 0.f;
        for (int t = 0; t < T; t++) acc += s_sc[t] * encb[(size_t)t * E + e];
        P.ctx[(size_t)b * E + e] = acc * inv;
    }
}

// ---------------------------------------------------------------------------
// Persistent fused chain: proj -> v2c -> ca_finish -> gih -> lstm
// Grid MUST be 128 blocks x 128 threads.
// ---------------------------------------------------------------------------
struct ChainParams {
    const float* ctxv; const float* ctxa;
    const float* W_venc; const float* W_aenc; const float* W_ca2;
    const float* v1c; const float* W_ca3; const float* input; const float* W_ih;
    const float* b_ih; const float* b_hh; const float* c0;
    float* allctx; float* v2c; float* x; float* gates;
    float* hsc; float* h_out; float* c_out;
};

__global__ void __launch_bounds__(128) fused_chain(ChainParams P)
{
    __shared__ uint32_t As[64][36];
    __shared__ uint32_t Bs[64][36];
    __shared__ float red0[4], red1[4];
    __shared__ float s_a0, s_a1;

    const int bid = blockIdx.x;
    const int tid = threadIdx.x;

    if (bid < 32) {
        if (bid < 16) {
            gemm_core(P.ctxv, 1024, P.W_venc, 1024, nullptr, P.allctx, 1024,
                      512, 1024, 0, (bid >> 3) << 6, (bid & 7) << 6, As, Bs);
        } else {
            const int t = bid - 16;
            gemm_core(P.ctxa, 512, P.W_aenc, 512, nullptr, P.allctx + 512, 1024,
                      512, 512, 0, (t >> 3) << 6, (t & 7) << 6, As, Bs);
        }
    }
    grid_bar(0, 128);

    if (bid < 32) {
        gemm_core(P.allctx, 512, P.W_ca2, 512, nullptr, P.v2c, 512,
                  512, 512, 0, (bid >> 3) << 6, (bid & 7) << 6, As, Bs);
    }
    grid_bar(1, 128);

    {
        const int b = bid;
        const int warp = tid >> 5, lane = tid & 31;
        const float* v1b = P.v1c + (size_t)b * 512;
        const float* v20 = P.v2c + (size_t)(2 * b) * 512;
        const float* v21 = v20 + 512;

        float p0 = 0.f, p1 = 0.f;
        for (int c = tid; c < 512; c += 128) {
            const float w = P.W_ca3[c];
            p0 += tanhf(v1b[c] + v20[c]) * w;
            p1 += tanhf(v1b[c] + v21[c]) * w;
        }
#pragma unroll
        for (int o = 16; o; o >>= 1) {
            p0 += __shfl_xor_sync(0xffffffffu, p0, o);
            p1 += __shfl_xor_sync(0xffffffffu, p1, o);
        }
        if (lane == 0) { red0[warp] = p0; red1[warp] = p1; }
        __syncthreads();
        if (tid == 0) {
            float s0 = red0[0] + red0[1] + red0[2] + red0[3];
            float s1 = red1[0] + red1[1] + red1[2] + red1[3];
            const float m = fmaxf(s0, s1);
            const float e0 = expf(s0 - m), e1 = expf(s1 - m);
            const float inv = 1.f / (e0 + e1);
            s_a0 = e0 * inv; s_a1 = e1 * inv;
        }
        __syncthreads();
        const float a0 = s_a0, a1 = s_a1;

        const float* ctx0 = P.allctx + (size_t)b * 1024;
        const float* ctx1 = ctx0 + 512;
        float* xb = P.x + (size_t)b * 1024;
        const float* ib = P.input + (size_t)b * 512;
        for (int e = tid; e < 512; e += 128) xb[e] = ib[e];
        for (int c = tid; c < 512; c += 128)
            xb[512 + c] = tanhf(a0 * ctx0[c] + a1 * ctx1[c]);
    }
    grid_bar(2, 128);

    {
        const int by = bid >> 6;
        const int bx = bid & 63;
        gemm_core(P.x, 1024, P.W_ih, 1024, nullptr, P.gates, 4096,
                  4096, 1024, 1, by << 6, bx << 6, As, Bs);
    }
    grid_bar(3, 128);

    for (int idx = bid * 128 + tid; idx < 128 * 1024; idx += 128 * 128) {
        const int b = idx >> 10, k = idx & 1023;
        const float* g = P.gates + (size_t)b * 4096;
        const float ig = g[k]        + P.b_ih[k]        + P.b_hh[k];
        const float fg = g[1024 + k] + P.b_ih[1024 + k] + P.b_hh[1024 + k];
        const float gg = g[2048 + k] + P.b_ih[2048 + k] + P.b_hh[2048 + k];
        const float og = g[3072 + k] + P.b_ih[3072 + k] + P.b_hh[3072 + k];

        const float si = 1.f / (1.f + expf(-ig));
        const float sf = 1.f / (1.f + expf(-fg));
        const float so = 1.f / (1.f + expf(-og));
        const float cn = sf * P.c0[idx] + si * tanhf(gg);
        const float hn = so * tanhf(cn);

        P.hsc[idx] = hn;
        P.h_out[idx] = hn;
        P.c_out[idx] = cn;
    }
}

// ---------------------------------------------------------------------------
// Launch
// ---------------------------------------------------------------------------
static inline GemmGroup mkgrp(const float* A, int lda, const float* B, int ldb,
                              const float* bias, float* C, int ldc,
                              int M, int N, int K, int accum, int prevEnd)
{
    GemmGroup g;
    g.A = A; g.B = B; g.bias = bias; g.C = C;
    g.lda = lda; g.ldb = ldb; g.ldc = ldc;
    g.N = N; g.K = K; g.accum = accum;
    g.nbx = (N + 63) / 64;
    g.end = prevEnd + g.nbx * (M / 64);
    return g;
}

extern "C" void kernel_launch(void* const* d_in, const int* in_sizes, int n_in,
                              void* d_out, int out_size)
{
    (void)in_sizes; (void)n_in; (void)out_size;

    float* S = nullptr;
    cudaGetSymbolAddress((void**)&S, g_scratch);

    const float* input  = (const float*)d_in[0];
    const float* enc_v  = (const float*)d_in[1];
    const float* enc_a  = (const float*)d_in[2];
    const float* h0     = (const float*)d_in[3];
    const float* c0     = (const float*)d_in[4];
    const float* W_va1  = (const float*)d_in[5];
    const float* W_va2  = (const float*)d_in[6];
    const float* W_va3  = (const float*)d_in[7];
    const float* W_venc = (const float*)d_in[8];
    const float* W_aa1  = (const float*)d_in[9];
    const float* W_aa2  = (const float*)d_in[10];
    const float* W_aa3  = (const float*)d_in[11];
    const float* W_aenc = (const float*)d_in[12];
    const float* W_ca1  = (const float*)d_in[13];
    const float* W_ca2  = (const float*)d_in[14];
    const float* W_ca3  = (const float*)d_in[15];
    const float* W_ih   = (const float*)d_in[16];
    const float* W_hh   = (const float*)d_in[17];
    const float* b_ih   = (const float*)d_in[18];
    const float* b_hh   = (const float*)d_in[19];
    const float* W_out  = (const float*)d_in[20];
    const float* b_out  = (const float*)d_in[21];

    float* out    = (float*)d_out;
    float* logits = out;
    float* h_out  = out + 128 * 20000;
    float* c_out  = h_out + 128 * 1024;

    float* v2v    = S + OFF_V2V;
    float* v2a    = S + OFF_V2A;
    float* v1v    = S + OFF_V1V;
    float* v1a    = S + OFF_V1A;
    float* v1c    = S + OFF_V1C;
    float* ctxv   = S + OFF_CTXV;
    float* ctxa   = S + OFF_CTXA;
    float* allctx = S + OFF_ALLCTX;
    float* v2c    = S + OFF_V2C;
    float* x      = S + OFF_X;
    float* gates  = S + OFF_GATES;
    float* hsc    = S + OFF_H;

    float* rencv = S + OFF_RENCV;
    float* renca = S + OFF_RENCA;
    float* rh    = S + OFF_RH;
    float* rwva2 = S + OFF_RWVA2;
    float* rwaa2 = S + OFF_RWAA2;
    float* rwhh  = S + OFF_RWHH;
    float* rwva1 = S + OFF_RWVA1;
    float* rwaa1 = S + OFF_RWAA1;
    float* rwca1 = S + OFF_RWCA1;

    // ---- launch 0: pre-round all launch-1 operands to tf32 ----
    SegList SL;
    SL.seg[0] = {enc_v, rencv, 8388608u / 4};
    SL.seg[1] = {enc_a, renca, 8388608u / 4};
    SL.seg[2] = {h0,    rh,    131072u  / 4};
    SL.seg[3] = {W_va2, rwva2, 524288u  / 4};
    SL.seg[4] = {W_aa2, rwaa2, 262144u  / 4};
    SL.seg[5] = {W_hh,  rwhh,  4194304u / 4};
    SL.seg[6] = {W_va1, rwva1, 524288u  / 4};
    SL.seg[7] = {W_aa1, rwaa1, 524288u  / 4};
    SL.seg[8] = {W_ca1, rwca1, 524288u  / 4};
    SL.tot4 = 0;
    for (int i = 0; i < 9; i++) SL.tot4 += SL.seg[i].n4;
    preround<<<2048, 256>>>(SL);

    // ---- launch 1: all input-only GEMMs on the new cp.async+ldmatrix core ----
    GemmList L1; L1.n = 6;
    L1.g[0] = mkgrp(renca, 512,  rwaa2, 512,  nullptr, v2a,   512,  16384, 512,  512,  0, 0);
    L1.g[1] = mkgrp(rencv, 1024, rwva2, 1024, nullptr, v2v,   512,  8192,  512,  1024, 0, L1.g[0].end);
    L1.g[2] = mkgrp(rh,    1024, rwhh,  1024, nullptr, gates, 4096, 128,   4096, 1024, 0, L1.g[1].end);
    L1.g[3] = mkgrp(rh,    1024, rwva1, 1024, nullptr, v1v,   512,  128,   512,  1024, 0, L1.g[2].end);
    L1.g[4] = mkgrp(rh,    1024, rwaa1, 1024, nullptr, v1a,   512,  128,   512,  1024, 0, L1.g[3].end);
    L1.g[5] = mkgrp(rh,    1024, rwca1, 1024, nullptr, v1c,   512,  128,   512,  1024, 0, L1.g[4].end);
    gemm_tcore<<<L1.g[5].end, 128>>>(L1);

    // ---- launch 2: both attentions ----
    AttParams Pv{v1v, v2v, W_va3, enc_v, ctxv, 64, 512, 1024};
    AttParams Pa{v1a, v2a, W_aa3, enc_a, ctxa, 128, 512, 512};
    attend_both<<<256, 256>>>(Pv, Pa);

    // ---- launch 3: persistent fused chain ----
    ChainParams CP;
    CP.ctxv = ctxv; CP.ctxa = ctxa;
    CP.W_venc = W_venc; CP.W_aenc = W_aenc; CP.W_ca2 = W_ca2;
    CP.v1c = v1c; CP.W_ca3 = W_ca3; CP.input = input; CP.W_ih = W_ih;
    CP.b_ih = b_ih; CP.b_hh = b_hh; CP.c0 = c0;
    CP.allctx = allctx; CP.v2c = v2c; CP.x = x; CP.gates = gates;
    CP.hsc = hsc; CP.h_out = h_out; CP.c_out = c_out;
    fused_chain<<<128, 128>>>(CP);

    // ---- launch 4: logits (old core; inline cvt) ----
    GemmList L5; L5.n = 1;
    L5.g[0] = mkgrp(hsc, 1024, W_out, 1024, b_out, logits, 20000, 128, 20000, 1024, 0, 0);
    gemm_grouped<<<L5.g[0].end, 128>>>(L5);
}

// round 7
// speedup vs baseline: 1.1431x; 1.1431x over previous
#include <cuda_runtime.h>
#include <cstdint>

// ---------------------------------------------------------------------------
// Problem constants
//   B=128, T_V=64, T_A=128, E_V=1024, E_A=512, H=1024, EMB=512, C=512
//   IN=1024, VOCAB=20000
// Output = [logits(128*20000) | h_new(128*1024) | c_new(128*1024)]
// ---------------------------------------------------------------------------

// Scratch offsets (floats)
#define OFF_V2V     0u            // 8192*512
#define OFF_V2A     4194304u      // 16384*512
#define OFF_V1V     12582912u     // 128*512
#define OFF_V1A     12648448u     // 128*512
#define OFF_V1C     12713984u     // 128*512
#define OFF_CTXV    12779520u     // 128*1024
#define OFF_CTXA    12910592u     // 128*512
#define OFF_ALLCTX  12976128u     // 128*2*512
#define OFF_V2C     13107200u     // 256*512
#define OFF_X2      13238272u     // 128*512
#define OFF_GATES   13369344u     // 128*4096
#define OFF_H       13893632u     // 128*1024
#define OFF_VTMP    14024704u     // 128*512
#define OFF_V2CTMP  14090240u     // 256*512
#define OFF_GATES2  14221312u     // 128*4096
#define SCRATCH_FLOATS 14745600u

__device__ float g_scratch[SCRATCH_FLOATS];
__device__ int g_bar[8];   // monotonic barrier counters (never reset; replay-safe)

__device__ __forceinline__ uint32_t f2tf(float f) {
    uint32_t u;
    asm("cvt.rna.tf32.f32 %0, %1;" : "=r"(u) : "f"(f));
    return u;
}

// Grid-wide barrier for a co-resident grid of nblk blocks. Tight spin.
__device__ __forceinline__ void grid_bar(int i, int nblk) {
    __syncthreads();
    if (threadIdx.x == 0) {
        __threadfence();
        int old = atomicAdd(&g_bar[i], 1);
        int goal = (old / nblk + 1) * nblk;
        volatile int* p = &g_bar[i];
        while (*p < goal) { }
        __threadfence();
    }
    __syncthreads();
}

// ---------------------------------------------------------------------------
// OLD TF32 core (register path + inline cvt) — proven; used for launch1.
// Tile 64x64x32, 128 threads, warp tile 32x32.
// ---------------------------------------------------------------------------
__device__ __forceinline__ void gemm_core(
    const float* __restrict__ A, int lda,
    const float* __restrict__ B, int ldb,
    const float* __restrict__ bias,
    float* __restrict__ C, int ldc,
    int N, int K, int accum,
    int mBase, int nBase,
    uint32_t (*As)[36], uint32_t (*Bs)[36])
{
    const int tid  = threadIdx.x;
    const int lane = tid & 31;
    const int warp = tid >> 5;
    const int wm = warp >> 1;
    const int wn = warp & 1;
    const int lr = tid >> 3;
    const int lc = tid & 7;

    float acc[2][4][4];
#pragma unroll
    for (int i = 0; i < 2; i++)
#pragma unroll
        for (int j = 0; j < 4; j++)
#pragma unroll
            for (int k = 0; k < 4; k++) acc[i][j][k] = 0.f;

    const int nk = K >> 5;
    float4 pa[4], pb[4];

    {
        const float* Ap = A + (size_t)(mBase + lr) * lda + (lc << 2);
#pragma unroll
        for (int i = 0; i < 4; i++)
            pa[i] = *(const float4*)(Ap + (size_t)(i * 16) * lda);
#pragma unroll
        for (int i = 0; i < 4; i++) {
            const int nr = nBase + lr + i * 16;
            pb[i] = (nr < N) ? *(const float4*)(B + (size_t)nr * ldb + (lc << 2))
                             : make_float4(0.f, 0.f, 0.f, 0.f);
        }
    }
#pragma unroll
    for (int i = 0; i < 4; i++) {
        const int r = lr + (i << 4);
        uint4 v;
        v.x = f2tf(pa[i].x); v.y = f2tf(pa[i].y); v.z = f2tf(pa[i].z); v.w = f2tf(pa[i].w);
        *(uint4*)&As[r][lc << 2] = v;
        uint4 w;
        w.x = f2tf(pb[i].x); w.y = f2tf(pb[i].y); w.z = f2tf(pb[i].z); w.w = f2tf(pb[i].w);
        *(uint4*)&Bs[r][lc << 2] = w;
    }

    for (int kt = 0; kt < nk; kt++) {
        __syncthreads();
        const bool more = (kt + 1 < nk);
        if (more) {
            const int ko = (kt + 1) << 5;
            const float* Ap = A + (size_t)(mBase + lr) * lda + ko + (lc << 2);
#pragma unroll
            for (int i = 0; i < 4; i++)
                pa[i] = *(const float4*)(Ap + (size_t)(i * 16) * lda);
#pragma unroll
            for (int i = 0; i < 4; i++) {
                const int nr = nBase + lr + i * 16;
                pb[i] = (nr < N)
                    ? *(const float4*)(B + (size_t)nr * ldb + ko + (lc << 2))
                    : make_float4(0.f, 0.f, 0.f, 0.f);
            }
        }

#pragma unroll
        for (int kk = 0; kk < 32; kk += 8) {
            uint32_t a[2][4], b[4][2];
            const int c = kk + (lane & 3);
#pragma unroll
            for (int im = 0; im < 2; im++) {
                const int r = (wm << 5) + (im << 4) + (lane >> 2);
                a[im][0] = As[r][c];
                a[im][1] = As[r + 8][c];
                a[im][2] = As[r][c + 4];
                a[im][3] = As[r + 8][c + 4];
            }
#pragma unroll
            for (int jn = 0; jn < 4; jn++) {
                const int nr = (wn << 5) + (jn << 3) + (lane >> 2);
                b[jn][0] = Bs[nr][c];
                b[jn][1] = Bs[nr][c + 4];
            }
#pragma unroll
            for (int im = 0; im < 2; im++)
#pragma unroll
                for (int jn = 0; jn < 4; jn++)
                    asm volatile(
                        "mma.sync.aligned.m16n8k8.row.col.f32.tf32.tf32.f32 "
                        "{%0,%1,%2,%3}, {%4,%5,%6,%7}, {%8,%9}, {%0,%1,%2,%3};"
                        : "+f"(acc[im][jn][0]), "+f"(acc[im][jn][1]),
                          "+f"(acc[im][jn][2]), "+f"(acc[im][jn][3])
                        : "r"(a[im][0]), "r"(a[im][1]), "r"(a[im][2]), "r"(a[im][3]),
                          "r"(b[jn][0]), "r"(b[jn][1]));
        }

        __syncthreads();
        if (more) {
#pragma unroll
            for (int i = 0; i < 4; i++) {
                const int r = lr + (i << 4);
                uint4 v;
                v.x = f2tf(pa[i].x); v.y = f2tf(pa[i].y); v.z = f2tf(pa[i].z); v.w = f2tf(pa[i].w);
                *(uint4*)&As[r][lc << 2] = v;
                uint4 w;
                w.x = f2tf(pb[i].x); w.y = f2tf(pb[i].y); w.z = f2tf(pb[i].z); w.w = f2tf(pb[i].w);
                *(uint4*)&Bs[r][lc << 2] = w;
            }
        }
    }

#pragma unroll
    for (int im = 0; im < 2; im++) {
        const int m0 = mBase + (wm << 5) + (im << 4) + (lane >> 2);
#pragma unroll
        for (int jn = 0; jn < 4; jn++) {
            const int n0 = nBase + (wn << 5) + (jn << 3) + ((lane & 3) << 1);
#pragma unroll
            for (int half = 0; half < 2; half++) {
                const int m = m0 + half * 8;
                const float v0 = acc[im][jn][half * 2 + 0];
                const float v1 = acc[im][jn][half * 2 + 1];
                if (n0 < N) {
                    float xv = v0 + (bias ? bias[n0] : 0.f);
                    if (accum) C[(size_t)m * ldc + n0] += xv;
                    else       C[(size_t)m * ldc + n0]  = xv;
                }
                if (n0 + 1 < N) {
                    float xv = v1 + (bias ? bias[n0 + 1] : 0.f);
                    if (accum) C[(size_t)m * ldc + n0 + 1] += xv;
                    else       C[(size_t)m * ldc + n0 + 1]  = xv;
                }
            }
        }
    }
}

struct GemmGroup {
    const float* A; const float* B; const float* bias; float* C;
    int lda, ldb, ldc, N, K, accum, nbx, end;
};
struct GemmList { GemmGroup g[8]; int n; };

__global__ void __launch_bounds__(128) gemm_grouped(GemmList L)
{
    __shared__ uint32_t As[64][36];
    __shared__ uint32_t Bs[64][36];

    const int bid = blockIdx.x;
    int gi = 0;
#pragma unroll
    for (int i = 0; i < 8; i++)
        if (i < L.n && bid >= L.g[i].end) gi = i + 1;
    const GemmGroup& G = L.g[gi];
    const int start = gi ? L.g[gi - 1].end : 0;
    const int lb = bid - start;
    const int by = lb / G.nbx;
    const int bx = lb - by * G.nbx;

    gemm_core(G.A, G.lda, G.B, G.ldb, G.bias, G.C, G.ldc,
              G.N, G.K, G.accum, by << 6, bx << 6, As, Bs);
}

// ---------------------------------------------------------------------------
// NEW async core: cp.async 2-stage + ldmatrix + in-register tf32 cvt.
// Numerics bit-identical to gemm_core (cvt.rna applied before every MMA).
// Tile 64x64x32, 128 threads. M%64==0, K%32==0, lda/ldb%4==0. N ragged OK
// (B row reads clamped to N-1; epilogue guarded).
// smem: sm[9216] uint32 = [A stage0|A stage1|B stage0|B stage1] (36864 B).
// ---------------------------------------------------------------------------
__device__ __forceinline__ void cp16(uint32_t dst, const float* src) {
    asm volatile("cp.async.ca.shared.global [%0], [%1], 16;"
                 :: "r"(dst), "l"(src));
}
__device__ __forceinline__ void cp_commit() {
    asm volatile("cp.async.commit_group;");
}
__device__ __forceinline__ void ldsm4(uint32_t* r, uint32_t addr) {
    asm volatile("ldmatrix.sync.aligned.m8n8.x4.shared.b16 {%0,%1,%2,%3}, [%4];"
                 : "=r"(r[0]), "=r"(r[1]), "=r"(r[2]), "=r"(r[3]) : "r"(addr));
}

__device__ __forceinline__ void gemm_async_core(
    const float* __restrict__ A, int lda,
    const float* __restrict__ B, int ldb,
    const float* __restrict__ bias,
    float* __restrict__ C, int ldc,
    int N, int K, int accum, int mBase, int nBase,
    uint32_t* sm)
{
    const int tid  = threadIdx.x;
    const int lane = tid & 31;
    const int warp = tid >> 5;
    const int wm = warp >> 1;
    const int wn = warp & 1;
    const int lr = tid >> 3;
    const int lc = tid & 7;
    const int nk = K >> 5;

    const float* aS[4]; const float* bS[4];
    uint32_t aD[4], bD[4];
#pragma unroll
    for (int i = 0; i < 4; i++) {
        aS[i] = A + (size_t)(mBase + lr + i * 16) * lda + (lc << 2);
        int nr = nBase + lr + i * 16;
        if (nr > N - 1) nr = N - 1;
        bS[i] = B + (size_t)nr * ldb + (lc << 2);
        aD[i] = (uint32_t)__cvta_generic_to_shared(sm + (lr + i * 16) * 36 + (lc << 2));
        bD[i] = (uint32_t)__cvta_generic_to_shared(sm + 4608 + (lr + i * 16) * 36 + (lc << 2));
    }

    auto issue = [&](int kt) {
        const int ko = kt << 5;
        const uint32_t so = (kt & 1) ? 9216u : 0u;   // stage byte offset
#pragma unroll
        for (int i = 0; i < 4; i++) cp16(aD[i] + so, aS[i] + ko);
#pragma unroll
        for (int i = 0; i < 4; i++) cp16(bD[i] + so, bS[i] + ko);
        cp_commit();
    };

    float acc[2][4][4];
#pragma unroll
    for (int i = 0; i < 2; i++)
#pragma unroll
        for (int j = 0; j < 4; j++)
#pragma unroll
            for (int k = 0; k < 4; k++) acc[i][j][k] = 0.f;

    issue(0);
    if (nk > 1) issue(1);

    const int l7 = lane & 7;
    const int q3 = (lane >> 3) & 1;
    const int q4 = (lane >> 4) & 1;
    const int aRow = (wm << 5) + l7 + (q3 << 3);
    const int aCol = (q4 << 2);
    const int bRow = (wn << 5) + l7 + (q4 << 3);
    const int bCol = (q3 << 2);

    for (int kt = 0; kt < nk; kt++) {
        if (kt < nk - 1) asm volatile("cp.async.wait_group 1;");
        else             asm volatile("cp.async.wait_group 0;");
        __syncthreads();

        const uint32_t sw = (kt & 1) ? 2304u : 0u;   // stage word offset
#pragma unroll
        for (int kk = 0; kk < 32; kk += 8) {
            uint32_t am[2][4], bm[2][4];
#pragma unroll
            for (int im = 0; im < 2; im++) {
                uint32_t addr = (uint32_t)__cvta_generic_to_shared(
                    sm + sw + (aRow + (im << 4)) * 36 + aCol + kk);
                ldsm4(am[im], addr);
            }
#pragma unroll
            for (int p = 0; p < 2; p++) {
                uint32_t addr = (uint32_t)__cvta_generic_to_shared(
                    sm + 4608 + sw + (bRow + (p << 4)) * 36 + bCol + kk);
                ldsm4(bm[p], addr);
            }
            // tf32 rounding on fragments (bit-identical to old core's numerics)
#pragma unroll
            for (int im = 0; im < 2; im++)
#pragma unroll
                for (int j = 0; j < 4; j++)
                    am[im][j] = f2tf(__uint_as_float(am[im][j]));
#pragma unroll
            for (int p = 0; p < 2; p++)
#pragma unroll
                for (int j = 0; j < 4; j++)
                    bm[p][j] = f2tf(__uint_as_float(bm[p][j]));

#pragma unroll
            for (int im = 0; im < 2; im++)
#pragma unroll
                for (int jn = 0; jn < 4; jn++) {
                    const uint32_t b0 = bm[jn >> 1][(jn & 1) << 1];
                    const uint32_t b1 = bm[jn >> 1][((jn & 1) << 1) + 1];
                    asm volatile(
                        "mma.sync.aligned.m16n8k8.row.col.f32.tf32.tf32.f32 "
                        "{%0,%1,%2,%3}, {%4,%5,%6,%7}, {%8,%9}, {%0,%1,%2,%3};"
                        : "+f"(acc[im][jn][0]), "+f"(acc[im][jn][1]),
                          "+f"(acc[im][jn][2]), "+f"(acc[im][jn][3])
                        : "r"(am[im][0]), "r"(am[im][1]), "r"(am[im][2]), "r"(am[im][3]),
                          "r"(b0), "r"(b1));
                }
        }

        __syncthreads();
        if (kt + 2 < nk) issue(kt + 2);
    }

#pragma unroll
    for (int im = 0; im < 2; im++) {
        const int m0 = mBase + (wm << 5) + (im << 4) + (lane >> 2);
#pragma unroll
        for (int jn = 0; jn < 4; jn++) {
            const int n0 = nBase + (wn << 5) + (jn << 3) + ((lane & 3) << 1);
#pragma unroll
            for (int half = 0; half < 2; half++) {
                const int m = m0 + half * 8;
                const float v0 = acc[im][jn][half * 2 + 0];
                const float v1 = acc[im][jn][half * 2 + 1];
                if (n0 < N) {
                    float xv = v0 + (bias ? bias[n0] : 0.f);
                    if (accum) C[(size_t)m * ldc + n0] += xv;
                    else       C[(size_t)m * ldc + n0]  = xv;
                }
                if (n0 + 1 < N) {
                    float xv = v1 + (bias ? bias[n0 + 1] : 0.f);
                    if (accum) C[(size_t)m * ldc + n0 + 1] += xv;
                    else       C[(size_t)m * ldc + n0 + 1]  = xv;
                }
            }
        }
    }
}

__global__ void __launch_bounds__(128) gemm_async_grouped(GemmList L)
{
    __shared__ uint32_t sm[9216];

    const int bid = blockIdx.x;
    int gi = 0;
#pragma unroll
    for (int i = 0; i < 8; i++)
        if (i < L.n && bid >= L.g[i].end) gi = i + 1;
    const GemmGroup& G = L.g[gi];
    const int start = gi ? L.g[gi - 1].end : 0;
    const int lb = bid - start;
    const int by = lb / G.nbx;
    const int bx = lb - by * G.nbx;

    gemm_async_core(G.A, G.lda, G.B, G.ldb, G.bias, G.C, G.ldc,
                    G.N, G.K, G.accum, by << 6, bx << 6, sm);
}

// ---------------------------------------------------------------------------
// Both Bahdanau attentions in one launch.
// ---------------------------------------------------------------------------
struct AttParams {
    const float* v1; const float* v2; const float* W3; const float* enc;
    float* ctx; int T, C, E;
};

__global__ void __launch_bounds__(256) attend_both(AttParams P0, AttParams P1)
{
    const AttParams P = (blockIdx.x >> 7) ? P1 : P0;
    const int b = blockIdx.x & 127;
    const int tid = threadIdx.x;
    const int warp = tid >> 5, lane = tid & 31;
    __shared__ float s_sc[128];
    __shared__ float s_inv;

    const int T = P.T, C = P.C, E = P.E;
    const float* v1b = P.v1 + (size_t)b * C;
    const float* v2b = P.v2 + (size_t)b * T * C;

    for (int t = warp; t < T; t += 8) {
        const float* row = v2b + (size_t)t * C;
        float acc = 0.f;
        for (int c = lane; c < C; c += 32)
            acc += tanhf(v1b[c] + row[c]) * P.W3[c];
#pragma unroll
        for (int o = 16; o; o >>= 1) acc += __shfl_xor_sync(0xffffffffu, acc, o);
        if (lane == 0) s_sc[t] = acc;
    }
    __syncthreads();

    if (tid == 0) {
        float m = -1e30f;
        for (int t = 0; t < T; t++) m = fmaxf(m, s_sc[t]);
        float s = 0.f;
        for (int t = 0; t < T; t++) { float e = expf(s_sc[t] - m); s_sc[t] = e; s += e; }
        s_inv = 1.f / s;
    }
    __syncthreads();
    const float inv = s_inv;

    const float* encb = P.enc + (size_t)b * T * E;
    for (int e = tid; e < E; e += 256) {
        float acc = 0.f;
        for (int t = 0; t < T; t++) acc += s_sc[t] * encb[(size_t)t * E + e];
        P.ctx[(size_t)b * E + e] = acc * inv;
    }
}

// ---------------------------------------------------------------------------
// Persistent fused chain with split-K parallelism.
// Grid MUST be 128 blocks x 128 threads (co-resident; tight-spin barriers).
// Phases: P1 proj(48 tasks, vis split-K) -> P1b reduce -> P2 v2c(64 tasks,
// split-K) -> P3 ca_finish (v2c reduce folded in) -> P4 gates += x2@W_ih2^T
// -> P5 lstm (adds gates2 = input@W_ih1^T computed in launch1).
// ---------------------------------------------------------------------------
struct ChainParams {
    const float* ctxv; const float* ctxa;
    const float* W_venc; const float* W_aenc; const float* W_ca2;
    const float* v1c; const float* W_ca3; const float* W_ih;
    const float* b_ih; const float* b_hh; const float* c0;
    float* allctx; float* vtmp; float* v2c; float* v2ctmp;
    float* x2; float* gates; const float* gates2;
    float* hsc; float* h_out; float* c_out;
};

__global__ void __launch_bounds__(128) fused_chain(ChainParams P)
{
    __shared__ uint32_t sm[9216];
    __shared__ float red0[4], red1[4];
    __shared__ float s_a0, s_a1;

    const int bid = blockIdx.x;
    const int tid = threadIdx.x;

    // ---- P1: proj (vis split-K=2 => 32 tasks, aud => 16 tasks) ----
    if (bid < 48) {
        if (bid < 16) {           // vis, K-chunk 0 -> allctx (interleaved)
            gemm_async_core(P.ctxv, 1024, P.W_venc, 1024, nullptr, P.allctx, 1024,
                            512, 512, 0, (bid >> 3) << 6, (bid & 7) << 6, sm);
        } else if (bid < 32) {    // vis, K-chunk 1 -> vtmp
            const int t = bid - 16;
            gemm_async_core(P.ctxv + 512, 1024, P.W_venc + 512, 1024, nullptr,
                            P.vtmp, 512,
                            512, 512, 0, (t >> 3) << 6, (t & 7) << 6, sm);
        } else {                  // aud -> allctx+512
            const int t = bid - 32;
            gemm_async_core(P.ctxa, 512, P.W_aenc, 512, nullptr, P.allctx + 512, 1024,
                            512, 512, 0, (t >> 3) << 6, (t & 7) << 6, sm);
        }
    }
    grid_bar(0, 128);

    // ---- P1b: reduce vis partials into allctx ----
    for (int u = bid * 128 + tid; u < 128 * 512; u += 128 * 128) {
        const int b = u >> 9, c = u & 511;
        P.allctx[(size_t)b * 1024 + c] += P.vtmp[u];
    }
    grid_bar(1, 128);

    // ---- P2: v2c[256,512] = allctx @ W_ca2^T, split-K=2 (64 tasks) ----
    if (bid < 64) {
        const int kc = bid >> 5;
        const int t = bid & 31;
        const float* Aa = P.allctx + kc * 256;
        const float* Bb = P.W_ca2 + kc * 256;
        float* Cc = kc ? P.v2ctmp : P.v2c;
        gemm_async_core(Aa, 512, Bb, 512, nullptr, Cc, 512,
                        512, 256, 0, (t >> 3) << 6, (t & 7) << 6, sm);
    }
    grid_bar(2, 128);

    // ---- P3: 2-way softmax + final ctx + x2 = tanh(final_ctx) ----
    {
        const int b = bid;
        const int warp = tid >> 5, lane = tid & 31;
        const float* v1b  = P.v1c + (size_t)b * 512;
        const float* v20  = P.v2c + (size_t)(2 * b) * 512;
        const float* v21  = v20 + 512;
        const float* v20t = P.v2ctmp + (size_t)(2 * b) * 512;
        const float* v21t = v20t + 512;

        float p0 = 0.f, p1 = 0.f;
        for (int c = tid; c < 512; c += 128) {
            const float w = P.W_ca3[c];
            p0 += tanhf(v1b[c] + v20[c] + v20t[c]) * w;
            p1 += tanhf(v1b[c] + v21[c] + v21t[c]) * w;
        }
#pragma unroll
        for (int o = 16; o; o >>= 1) {
            p0 += __shfl_xor_sync(0xffffffffu, p0, o);
            p1 += __shfl_xor_sync(0xffffffffu, p1, o);
        }
        if (lane == 0) { red0[warp] = p0; red1[warp] = p1; }
        __syncthreads();
        if (tid == 0) {
            float s0 = red0[0] + red0[1] + red0[2] + red0[3];
            float s1 = red1[0] + red1[1] + red1[2] + red1[3];
            const float m = fmaxf(s0, s1);
            const float e0 = expf(s0 - m), e1 = expf(s1 - m);
            const float inv = 1.f / (e0 + e1);
            s_a0 = e0 * inv; s_a1 = e1 * inv;
        }
        __syncthreads();
        const float a0 = s_a0, a1 = s_a1;

        const float* ctx0 = P.allctx + (size_t)b * 1024;
        const float* ctx1 = ctx0 + 512;
        float* xb = P.x2 + (size_t)b * 512;
        for (int c = tid; c < 512; c += 128)
            xb[c] = tanhf(a0 * ctx0[c] + a1 * ctx1[c]);
    }
    grid_bar(3, 128);

    // ---- P4: gates += x2 @ W_ih[:,512:]^T (128 tasks) ----
    {
        const int by = bid >> 6;
        const int bx = bid & 63;
        gemm_async_core(P.x2, 512, P.W_ih + 512, 1024, nullptr, P.gates, 4096,
                        4096, 512, 1, by << 6, bx << 6, sm);
    }
    grid_bar(4, 128);

    // ---- P5: LSTM pointwise (gates + gates2 + biases) ----
    for (int idx = bid * 128 + tid; idx < 128 * 1024; idx += 128 * 128) {
        const int b = idx >> 10, k = idx & 1023;
        const float* g  = P.gates  + (size_t)b * 4096;
        const float* g2 = P.gates2 + (size_t)b * 4096;
        const float ig = g[k]        + g2[k]        + P.b_ih[k]        + P.b_hh[k];
        const float fg = g[1024 + k] + g2[1024 + k] + P.b_ih[1024 + k] + P.b_hh[1024 + k];
        const float gg = g[2048 + k] + g2[2048 + k] + P.b_ih[2048 + k] + P.b_hh[2048 + k];
        const float og = g[3072 + k] + g2[3072 + k] + P.b_ih[3072 + k] + P.b_hh[3072 + k];

        const float si = 1.f / (1.f + expf(-ig));
        const float sf = 1.f / (1.f + expf(-fg));
        const float so = 1.f / (1.f + expf(-og));
        const float cn = sf * P.c0[idx] + si * tanhf(gg);
        const float hn = so * tanhf(cn);

        P.hsc[idx] = hn;
        P.h_out[idx] = hn;
        P.c_out[idx] = cn;
    }
}

// ---------------------------------------------------------------------------
// Launch
// ---------------------------------------------------------------------------
static inline GemmGroup mkgrp(const float* A, int lda, const float* B, int ldb,
                              const float* bias, float* C, int ldc,
                              int M, int N, int K, int accum, int prevEnd)
{
    GemmGroup g;
    g.A = A; g.B = B; g.bias = bias; g.C = C;
    g.lda = lda; g.ldb = ldb; g.ldc = ldc;
    g.N = N; g.K = K; g.accum = accum;
    g.nbx = (N + 63) / 64;
    g.end = prevEnd + g.nbx * (M / 64);
    return g;
}

extern "C" void kernel_launch(void* const* d_in, const int* in_sizes, int n_in,
                              void* d_out, int out_size)
{
    (void)in_sizes; (void)n_in; (void)out_size;

    float* S = nullptr;
    cudaGetSymbolAddress((void**)&S, g_scratch);

    const float* input  = (const float*)d_in[0];
    const float* enc_v  = (const float*)d_in[1];
    const float* enc_a  = (const float*)d_in[2];
    const float* h0     = (const float*)d_in[3];
    const float* c0     = (const float*)d_in[4];
    const float* W_va1  = (const float*)d_in[5];
    const float* W_va2  = (const float*)d_in[6];
    const float* W_va3  = (const float*)d_in[7];
    const float* W_venc = (const float*)d_in[8];
    const float* W_aa1  = (const float*)d_in[9];
    const float* W_aa2  = (const float*)d_in[10];
    const float* W_aa3  = (const float*)d_in[11];
    const float* W_aenc = (const float*)d_in[12];
    const float* W_ca1  = (const float*)d_in[13];
    const float* W_ca2  = (const float*)d_in[14];
    const float* W_ca3  = (const float*)d_in[15];
    const float* W_ih   = (const float*)d_in[16];
    const float* W_hh   = (const float*)d_in[17];
    const float* b_ih   = (const float*)d_in[18];
    const float* b_hh   = (const float*)d_in[19];
    const float* W_out  = (const float*)d_in[20];
    const float* b_out  = (const float*)d_in[21];

    float* out    = (float*)d_out;
    float* logits = out;
    float* h_out  = out + 128 * 20000;
    float* c_out  = h_out + 128 * 1024;

    float* v2v    = S + OFF_V2V;
    float* v2a    = S + OFF_V2A;
    float* v1v    = S + OFF_V1V;
    float* v1a    = S + OFF_V1A;
    float* v1c    = S + OFF_V1C;
    float* ctxv   = S + OFF_CTXV;
    float* ctxa   = S + OFF_CTXA;
    float* allctx = S + OFF_ALLCTX;
    float* v2c    = S + OFF_V2C;
    float* x2     = S + OFF_X2;
    float* gates  = S + OFF_GATES;
    float* hsc    = S + OFF_H;
    float* vtmp   = S + OFF_VTMP;
    float* v2ctmp = S + OFF_V2CTMP;
    float* gates2 = S + OFF_GATES2;

    // ---- launch 1: everything that depends only on inputs (old core) ----
    GemmList L1; L1.n = 7;
    L1.g[0] = mkgrp(enc_a, 512,  W_aa2, 512,  nullptr, v2a,    512,  16384, 512,  512,  0, 0);
    L1.g[1] = mkgrp(enc_v, 1024, W_va2, 1024, nullptr, v2v,    512,  8192,  512,  1024, 0, L1.g[0].end);
    L1.g[2] = mkgrp(h0,    1024, W_hh,  1024, nullptr, gates,  4096, 128,   4096, 1024, 0, L1.g[1].end);
    L1.g[3] = mkgrp(input, 512,  W_ih,  1024, nullptr, gates2, 4096, 128,   4096, 512,  0, L1.g[2].end);
    L1.g[4] = mkgrp(h0,    1024, W_va1, 1024, nullptr, v1v,    512,  128,   512,  1024, 0, L1.g[3].end);
    L1.g[5] = mkgrp(h0,    1024, W_aa1, 1024, nullptr, v1a,    512,  128,   512,  1024, 0, L1.g[4].end);
    L1.g[6] = mkgrp(h0,    1024, W_ca1, 1024, nullptr, v1c,    512,  128,   512,  1024, 0, L1.g[5].end);
    gemm_grouped<<<L1.g[6].end, 128>>>(L1);

    // ---- launch 2: both attentions ----
    AttParams Pv{v1v, v2v, W_va3, enc_v, ctxv, 64, 512, 1024};
    AttParams Pa{v1a, v2a, W_aa3, enc_a, ctxa, 128, 512, 512};
    attend_both<<<256, 256>>>(Pv, Pa);

    // ---- launch 3: persistent fused chain ----
    ChainParams CP;
    CP.ctxv = ctxv; CP.ctxa = ctxa;
    CP.W_venc = W_venc; CP.W_aenc = W_aenc; CP.W_ca2 = W_ca2;
    CP.v1c = v1c; CP.W_ca3 = W_ca3; CP.W_ih = W_ih;
    CP.b_ih = b_ih; CP.b_hh = b_hh; CP.c0 = c0;
    CP.allctx = allctx; CP.vtmp = vtmp; CP.v2c = v2c; CP.v2ctmp = v2ctmp;
    CP.x2 = x2; CP.gates = gates; CP.gates2 = gates2;
    CP.hsc = hsc; CP.h_out = h_out; CP.c_out = c_out;
    fused_chain<<<128, 128>>>(CP);

    // ---- launch 4: logits on the async core ----
    GemmList L5; L5.n = 1;
    L5.g[0] = mkgrp(hsc, 1024, W_out, 1024, b_out, logits, 20000, 128, 20000, 1024, 0, 0);
    gemm_async_grouped<<<L5.g[0].end, 128>>>(L5);
}

// round 8
// speedup vs baseline: 1.1772x; 1.0298x over previous
#include <cuda_runtime.h>
#include <cstdint>

// ---------------------------------------------------------------------------
// Problem constants
//   B=128, T_V=64, T_A=128, E_V=1024, E_A=512, H=1024, EMB=512, C=512
//   IN=1024, VOCAB=20000
// Output = [logits(128*20000) | h_new(128*1024) | c_new(128*1024)]
// ---------------------------------------------------------------------------

// Scratch offsets (floats)
#define OFF_V2V     0u            // 8192*512
#define OFF_V2A     4194304u      // 16384*512
#define OFF_V1V     12582912u     // 128*512
#define OFF_V1A     12648448u     // 128*512
#define OFF_V1C     12713984u     // 128*512
#define OFF_CTXV    12779520u     // 128*1024
#define OFF_CTXA    12910592u     // 128*512
#define OFF_ALLCTX  12976128u     // 128*2*512
#define OFF_V2C     13107200u     // 256*512
#define OFF_X2      13238272u     // 128*512
#define OFF_GATES   13369344u     // 128*4096
#define OFF_H       13893632u     // 128*1024
#define OFF_VTMP    14024704u     // 128*512
#define OFF_V2CTMP  14090240u     // 256*512
#define OFF_GATES2  14221312u     // 128*4096
#define SCRATCH_FLOATS 14745600u

__device__ float g_scratch[SCRATCH_FLOATS];
__device__ int g_bar[8];   // monotonic barrier counters (never reset; replay-safe)

__device__ __forceinline__ uint32_t f2tf(float f) {
    uint32_t u;
    asm("cvt.rna.tf32.f32 %0, %1;" : "=r"(u) : "f"(f));
    return u;
}

// Grid-wide barrier for a co-resident grid of nblk blocks. Tight spin.
__device__ __forceinline__ void grid_bar(int i, int nblk) {
    __syncthreads();
    if (threadIdx.x == 0) {
        __threadfence();
        int old = atomicAdd(&g_bar[i], 1);
        int goal = (old / nblk + 1) * nblk;
        volatile int* p = &g_bar[i];
        while (*p < goal) { }
        __threadfence();
    }
    __syncthreads();
}

// ---------------------------------------------------------------------------
// Async TF32 core: cp.async 2-stage + ldmatrix + in-register tf32 cvt.
// Tile 64x64x32, 128 threads. M%64==0, K%32==0, lda/ldb%4==0. N ragged OK
// (B row reads clamped to N-1; epilogue guarded).
// smem: sm[9216] uint32 = [A stage0|A stage1|B stage0|B stage1] (36864 B).
// ---------------------------------------------------------------------------
__device__ __forceinline__ void cp16(uint32_t dst, const float* src) {
    asm volatile("cp.async.ca.shared.global [%0], [%1], 16;"
                 :: "r"(dst), "l"(src));
}
__device__ __forceinline__ void cp_commit() {
    asm volatile("cp.async.commit_group;");
}
__device__ __forceinline__ void ldsm4(uint32_t* r, uint32_t addr) {
    asm volatile("ldmatrix.sync.aligned.m8n8.x4.shared.b16 {%0,%1,%2,%3}, [%4];"
                 : "=r"(r[0]), "=r"(r[1]), "=r"(r[2]), "=r"(r[3]) : "r"(addr));
}

__device__ __forceinline__ void gemm_async_core(
    const float* __restrict__ A, int lda,
    const float* __restrict__ B, int ldb,
    const float* __restrict__ bias,
    float* __restrict__ C, int ldc,
    int N, int K, int accum, int mBase, int nBase,
    uint32_t* sm)
{
    const int tid  = threadIdx.x;
    const int lane = tid & 31;
    const int warp = tid >> 5;
    const int wm = warp >> 1;
    const int wn = warp & 1;
    const int lr = tid >> 3;
    const int lc = tid & 7;
    const int nk = K >> 5;

    const float* aS[4]; const float* bS[4];
    uint32_t aD[4], bD[4];
#pragma unroll
    for (int i = 0; i < 4; i++) {
        aS[i] = A + (size_t)(mBase + lr + i * 16) * lda + (lc << 2);
        int nr = nBase + lr + i * 16;
        if (nr > N - 1) nr = N - 1;
        bS[i] = B + (size_t)nr * ldb + (lc << 2);
        aD[i] = (uint32_t)__cvta_generic_to_shared(sm + (lr + i * 16) * 36 + (lc << 2));
        bD[i] = (uint32_t)__cvta_generic_to_shared(sm + 4608 + (lr + i * 16) * 36 + (lc << 2));
    }

    auto issue = [&](int kt) {
        const int ko = kt << 5;
        const uint32_t so = (kt & 1) ? 9216u : 0u;   // stage byte offset
#pragma unroll
        for (int i = 0; i < 4; i++) cp16(aD[i] + so, aS[i] + ko);
#pragma unroll
        for (int i = 0; i < 4; i++) cp16(bD[i] + so, bS[i] + ko);
        cp_commit();
    };

    float acc[2][4][4];
#pragma unroll
    for (int i = 0; i < 2; i++)
#pragma unroll
        for (int j = 0; j < 4; j++)
#pragma unroll
            for (int k = 0; k < 4; k++) acc[i][j][k] = 0.f;

    issue(0);
    if (nk > 1) issue(1);

    const int l7 = lane & 7;
    const int q3 = (lane >> 3) & 1;
    const int q4 = (lane >> 4) & 1;
    const int aRow = (wm << 5) + l7 + (q3 << 3);
    const int aCol = (q4 << 2);
    const int bRow = (wn << 5) + l7 + (q4 << 3);
    const int bCol = (q3 << 2);

    for (int kt = 0; kt < nk; kt++) {
        if (kt < nk - 1) asm volatile("cp.async.wait_group 1;");
        else             asm volatile("cp.async.wait_group 0;");
        __syncthreads();

        const uint32_t sw = (kt & 1) ? 2304u : 0u;   // stage word offset
#pragma unroll
        for (int kk = 0; kk < 32; kk += 8) {
            uint32_t am[2][4], bm[2][4];
#pragma unroll
            for (int im = 0; im < 2; im++) {
                uint32_t addr = (uint32_t)__cvta_generic_to_shared(
                    sm + sw + (aRow + (im << 4)) * 36 + aCol + kk);
                ldsm4(am[im], addr);
            }
#pragma unroll
            for (int p = 0; p < 2; p++) {
                uint32_t addr = (uint32_t)__cvta_generic_to_shared(
                    sm + 4608 + sw + (bRow + (p << 4)) * 36 + bCol + kk);
                ldsm4(bm[p], addr);
            }
            // tf32 rounding on fragments (bit-identical numerics everywhere)
#pragma unroll
            for (int im = 0; im < 2; im++)
#pragma unroll
                for (int j = 0; j < 4; j++)
                    am[im][j] = f2tf(__uint_as_float(am[im][j]));
#pragma unroll
            for (int p = 0; p < 2; p++)
#pragma unroll
                for (int j = 0; j < 4; j++)
                    bm[p][j] = f2tf(__uint_as_float(bm[p][j]));

#pragma unroll
            for (int im = 0; im < 2; im++)
#pragma unroll
                for (int jn = 0; jn < 4; jn++) {
                    const uint32_t b0 = bm[jn >> 1][(jn & 1) << 1];
                    const uint32_t b1 = bm[jn >> 1][((jn & 1) << 1) + 1];
                    asm volatile(
                        "mma.sync.aligned.m16n8k8.row.col.f32.tf32.tf32.f32 "
                        "{%0,%1,%2,%3}, {%4,%5,%6,%7}, {%8,%9}, {%0,%1,%2,%3};"
                        : "+f"(acc[im][jn][0]), "+f"(acc[im][jn][1]),
                          "+f"(acc[im][jn][2]), "+f"(acc[im][jn][3])
                        : "r"(am[im][0]), "r"(am[im][1]), "r"(am[im][2]), "r"(am[im][3]),
                          "r"(b0), "r"(b1));
                }
        }

        __syncthreads();
        if (kt + 2 < nk) issue(kt + 2);
    }

#pragma unroll
    for (int im = 0; im < 2; im++) {
        const int m0 = mBase + (wm << 5) + (im << 4) + (lane >> 2);
#pragma unroll
        for (int jn = 0; jn < 4; jn++) {
            const int n0 = nBase + (wn << 5) + (jn << 3) + ((lane & 3) << 1);
#pragma unroll
            for (int half = 0; half < 2; half++) {
                const int m = m0 + half * 8;
                const float v0 = acc[im][jn][half * 2 + 0];
                const float v1 = acc[im][jn][half * 2 + 1];
                if (n0 < N) {
                    float xv = v0 + (bias ? bias[n0] : 0.f);
                    if (accum) C[(size_t)m * ldc + n0] += xv;
                    else       C[(size_t)m * ldc + n0]  = xv;
                }
                if (n0 + 1 < N) {
                    float xv = v1 + (bias ? bias[n0 + 1] : 0.f);
                    if (accum) C[(size_t)m * ldc + n0 + 1] += xv;
                    else       C[(size_t)m * ldc + n0 + 1]  = xv;
                }
            }
        }
    }
}

struct GemmGroup {
    const float* A; const float* B; const float* bias; float* C;
    int lda, ldb, ldc, N, K, accum, nbx, end;
};
struct GemmList { GemmGroup g[8]; int n; };

__global__ void __launch_bounds__(128) gemm_async_grouped(GemmList L)
{
    __shared__ uint32_t sm[9216];

    const int bid = blockIdx.x;
    int gi = 0;
#pragma unroll
    for (int i = 0; i < 8; i++)
        if (i < L.n && bid >= L.g[i].end) gi = i + 1;
    const GemmGroup& G = L.g[gi];
    const int start = gi ? L.g[gi - 1].end : 0;
    const int lb = bid - start;
    const int by = lb / G.nbx;
    const int bx = lb - by * G.nbx;

    gemm_async_core(G.A, G.lda, G.B, G.ldb, G.bias, G.C, G.ldc,
                    G.N, G.K, G.accum, by << 6, bx << 6, sm);
}

// ---------------------------------------------------------------------------
// Both Bahdanau attentions in one launch.
// ---------------------------------------------------------------------------
struct AttParams {
    const float* v1; const float* v2; const float* W3; const float* enc;
    float* ctx; int T, C, E;
};

__global__ void __launch_bounds__(256) attend_both(AttParams P0, AttParams P1)
{
    const AttParams P = (blockIdx.x >> 7) ? P1 : P0;
    const int b = blockIdx.x & 127;
    const int tid = threadIdx.x;
    const int warp = tid >> 5, lane = tid & 31;
    __shared__ float s_sc[128];
    __shared__ float s_inv;

    const int T = P.T, C = P.C, E = P.E;
    const float* v1b = P.v1 + (size_t)b * C;
    const float* v2b = P.v2 + (size_t)b * T * C;

    for (int t = warp; t < T; t += 8) {
        const float* row = v2b + (size_t)t * C;
        float acc = 0.f;
        for (int c = lane; c < C; c += 32)
            acc += tanhf(v1b[c] + row[c]) * P.W3[c];
#pragma unroll
        for (int o = 16; o; o >>= 1) acc += __shfl_xor_sync(0xffffffffu, acc, o);
        if (lane == 0) s_sc[t] = acc;
    }
    __syncthreads();

    if (tid == 0) {
        float m = -1e30f;
        for (int t = 0; t < T; t++) m = fmaxf(m, s_sc[t]);
        float s = 0.f;
        for (int t = 0; t < T; t++) { float e = expf(s_sc[t] - m); s_sc[t] = e; s += e; }
        s_inv = 1.f / s;
    }
    __syncthreads();
    const float inv = s_inv;

    const float* encb = P.enc + (size_t)b * T * E;
    for (int e = tid; e < E; e += 256) {
        float acc = 0.f;
        for (int t = 0; t < T; t++) acc += s_sc[t] * encb[(size_t)t * E + e];
        P.ctx[(size_t)b * E + e] = acc * inv;
    }
}

// ---------------------------------------------------------------------------
// Persistent fused chain with split-K parallelism.
// Grid MUST be 128 blocks x 128 threads (co-resident; tight-spin barriers).
// ---------------------------------------------------------------------------
struct ChainParams {
    const float* ctxv; const float* ctxa;
    const float* W_venc; const float* W_aenc; const float* W_ca2;
    const float* v1c; const float* W_ca3; const float* W_ih;
    const float* b_ih; const float* b_hh; const float* c0;
    float* allctx; float* vtmp; float* v2c; float* v2ctmp;
    float* x2; float* gates; const float* gates2;
    float* hsc; float* h_out; float* c_out;
};

__global__ void __launch_bounds__(128) fused_chain(ChainParams P)
{
    __shared__ uint32_t sm[9216];
    __shared__ float red0[4], red1[4];
    __shared__ float s_a0, s_a1;

    const int bid = blockIdx.x;
    const int tid = threadIdx.x;

    // ---- P1: proj (vis split-K=2 => 32 tasks, aud => 16 tasks) ----
    if (bid < 48) {
        if (bid < 16) {
            gemm_async_core(P.ctxv, 1024, P.W_venc, 1024, nullptr, P.allctx, 1024,
                            512, 512, 0, (bid >> 3) << 6, (bid & 7) << 6, sm);
        } else if (bid < 32) {
            const int t = bid - 16;
            gemm_async_core(P.ctxv + 512, 1024, P.W_venc + 512, 1024, nullptr,
                            P.vtmp, 512,
                            512, 512, 0, (t >> 3) << 6, (t & 7) << 6, sm);
        } else {
            const int t = bid - 32;
            gemm_async_core(P.ctxa, 512, P.W_aenc, 512, nullptr, P.allctx + 512, 1024,
                            512, 512, 0, (t >> 3) << 6, (t & 7) << 6, sm);
        }
    }
    grid_bar(0, 128);

    // ---- P1b: reduce vis partials into allctx ----
    for (int u = bid * 128 + tid; u < 128 * 512; u += 128 * 128) {
        const int b = u >> 9, c = u & 511;
        P.allctx[(size_t)b * 1024 + c] += P.vtmp[u];
    }
    grid_bar(1, 128);

    // ---- P2: v2c[256,512] = allctx @ W_ca2^T, split-K=2 (64 tasks) ----
    if (bid < 64) {
        const int kc = bid >> 5;
        const int t = bid & 31;
        const float* Aa = P.allctx + kc * 256;
        const float* Bb = P.W_ca2 + kc * 256;
        float* Cc = kc ? P.v2ctmp : P.v2c;
        gemm_async_core(Aa, 512, Bb, 512, nullptr, Cc, 512,
                        512, 256, 0, (t >> 3) << 6, (t & 7) << 6, sm);
    }
    grid_bar(2, 128);

    // ---- P3: 2-way softmax + final ctx + x2 = tanh(final_ctx) ----
    {
        const int b = bid;
        const int warp = tid >> 5, lane = tid & 31;
        const float* v1b  = P.v1c + (size_t)b * 512;
        const float* v20  = P.v2c + (size_t)(2 * b) * 512;
        const float* v21  = v20 + 512;
        const float* v20t = P.v2ctmp + (size_t)(2 * b) * 512;
        const float* v21t = v20t + 512;

        float p0 = 0.f, p1 = 0.f;
        for (int c = tid; c < 512; c += 128) {
            const float w = P.W_ca3[c];
            p0 += tanhf(v1b[c] + v20[c] + v20t[c]) * w;
            p1 += tanhf(v1b[c] + v21[c] + v21t[c]) * w;
        }
#pragma unroll
        for (int o = 16; o; o >>= 1) {
            p0 += __shfl_xor_sync(0xffffffffu, p0, o);
            p1 += __shfl_xor_sync(0xffffffffu, p1, o);
        }
        if (lane == 0) { red0[warp] = p0; red1[warp] = p1; }
        __syncthreads();
        if (tid == 0) {
            float s0 = red0[0] + red0[1] + red0[2] + red0[3];
            float s1 = red1[0] + red1[1] + red1[2] + red1[3];
            const float m = fmaxf(s0, s1);
            const float e0 = expf(s0 - m), e1 = expf(s1 - m);
            const float inv = 1.f / (e0 + e1);
            s_a0 = e0 * inv; s_a1 = e1 * inv;
        }
        __syncthreads();
        const float a0 = s_a0, a1 = s_a1;

        const float* ctx0 = P.allctx + (size_t)b * 1024;
        const float* ctx1 = ctx0 + 512;
        float* xb = P.x2 + (size_t)b * 512;
        for (int c = tid; c < 512; c += 128)
            xb[c] = tanhf(a0 * ctx0[c] + a1 * ctx1[c]);
    }
    grid_bar(3, 128);

    // ---- P4: gates += x2 @ W_ih[:,512:]^T (128 tasks) ----
    {
        const int by = bid >> 6;
        const int bx = bid & 63;
        gemm_async_core(P.x2, 512, P.W_ih + 512, 1024, nullptr, P.gates, 4096,
                        4096, 512, 1, by << 6, bx << 6, sm);
    }
    grid_bar(4, 128);

    // ---- P5: LSTM pointwise (gates + gates2 + biases) ----
    for (int idx = bid * 128 + tid; idx < 128 * 1024; idx += 128 * 128) {
        const int b = idx >> 10, k = idx & 1023;
        const float* g  = P.gates  + (size_t)b * 4096;
        const float* g2 = P.gates2 + (size_t)b * 4096;
        const float ig = g[k]        + g2[k]        + P.b_ih[k]        + P.b_hh[k];
        const float fg = g[1024 + k] + g2[1024 + k] + P.b_ih[1024 + k] + P.b_hh[1024 + k];
        const float gg = g[2048 + k] + g2[2048 + k] + P.b_ih[2048 + k] + P.b_hh[2048 + k];
        const float og = g[3072 + k] + g2[3072 + k] + P.b_ih[3072 + k] + P.b_hh[3072 + k];

        const float si = 1.f / (1.f + expf(-ig));
        const float sf = 1.f / (1.f + expf(-fg));
        const float so = 1.f / (1.f + expf(-og));
        const float cn = sf * P.c0[idx] + si * tanhf(gg);
        const float hn = so * tanhf(cn);

        P.hsc[idx] = hn;
        P.h_out[idx] = hn;
        P.c_out[idx] = cn;
    }
}

// ---------------------------------------------------------------------------
// Launch
// ---------------------------------------------------------------------------
static inline GemmGroup mkgrp(const float* A, int lda, const float* B, int ldb,
                              const float* bias, float* C, int ldc,
                              int M, int N, int K, int accum, int prevEnd)
{
    GemmGroup g;
    g.A = A; g.B = B; g.bias = bias; g.C = C;
    g.lda = lda; g.ldb = ldb; g.ldc = ldc;
    g.N = N; g.K = K; g.accum = accum;
    g.nbx = (N + 63) / 64;
    g.end = prevEnd + g.nbx * (M / 64);
    return g;
}

extern "C" void kernel_launch(void* const* d_in, const int* in_sizes, int n_in,
                              void* d_out, int out_size)
{
    (void)in_sizes; (void)n_in; (void)out_size;

    float* S = nullptr;
    cudaGetSymbolAddress((void**)&S, g_scratch);

    const float* input  = (const float*)d_in[0];
    const float* enc_v  = (const float*)d_in[1];
    const float* enc_a  = (const float*)d_in[2];
    const float* h0     = (const float*)d_in[3];
    const float* c0     = (const float*)d_in[4];
    const float* W_va1  = (const float*)d_in[5];
    const float* W_va2  = (const float*)d_in[6];
    const float* W_va3  = (const float*)d_in[7];
    const float* W_venc = (const float*)d_in[8];
    const float* W_aa1  = (const float*)d_in[9];
    const float* W_aa2  = (const float*)d_in[10];
    const float* W_aa3  = (const float*)d_in[11];
    const float* W_aenc = (const float*)d_in[12];
    const float* W_ca1  = (const float*)d_in[13];
    const float* W_ca2  = (const float*)d_in[14];
    const float* W_ca3  = (const float*)d_in[15];
    const float* W_ih   = (const float*)d_in[16];
    const float* W_hh   = (const float*)d_in[17];
    const float* b_ih   = (const float*)d_in[18];
    const float* b_hh   = (const float*)d_in[19];
    const float* W_out  = (const float*)d_in[20];
    const float* b_out  = (const float*)d_in[21];

    float* out    = (float*)d_out;
    float* logits = out;
    float* h_out  = out + 128 * 20000;
    float* c_out  = h_out + 128 * 1024;

    float* v2v    = S + OFF_V2V;
    float* v2a    = S + OFF_V2A;
    float* v1v    = S + OFF_V1V;
    float* v1a    = S + OFF_V1A;
    float* v1c    = S + OFF_V1C;
    float* ctxv   = S + OFF_CTXV;
    float* ctxa   = S + OFF_CTXA;
    float* allctx = S + OFF_ALLCTX;
    float* v2c    = S + OFF_V2C;
    float* x2     = S + OFF_X2;
    float* gates  = S + OFF_GATES;
    float* hsc    = S + OFF_H;
    float* vtmp   = S + OFF_VTMP;
    float* v2ctmp = S + OFF_V2CTMP;
    float* gates2 = S + OFF_GATES2;

    // ---- launch 1: everything that depends only on inputs (async core) ----
    GemmList L1; L1.n = 7;
    L1.g[0] = mkgrp(enc_a, 512,  W_aa2, 512,  nullptr, v2a,    512,  16384, 512,  512,  0, 0);
    L1.g[1] = mkgrp(enc_v, 1024, W_va2, 1024, nullptr, v2v,    512,  8192,  512,  1024, 0, L1.g[0].end);
    L1.g[2] = mkgrp(h0,    1024, W_hh,  1024, nullptr, gates,  4096, 128,   4096, 1024, 0, L1.g[1].end);
    L1.g[3] = mkgrp(input, 512,  W_ih,  1024, nullptr, gates2, 4096, 128,   4096, 512,  0, L1.g[2].end);
    L1.g[4] = mkgrp(h0,    1024, W_va1, 1024, nullptr, v1v,    512,  128,   512,  1024, 0, L1.g[3].end);
    L1.g[5] = mkgrp(h0,    1024, W_aa1, 1024, nullptr, v1a,    512,  128,   512,  1024, 0, L1.g[4].end);
    L1.g[6] = mkgrp(h0,    1024, W_ca1, 1024, nullptr, v1c,    512,  128,   512,  1024, 0, L1.g[5].end);
    gemm_async_grouped<<<L1.g[6].end, 128>>>(L1);

    // ---- launch 2: both attentions ----
    AttParams Pv{v1v, v2v, W_va3, enc_v, ctxv, 64, 512, 1024};
    AttParams Pa{v1a, v2a, W_aa3, enc_a, ctxa, 128, 512, 512};
    attend_both<<<256, 256>>>(Pv, Pa);

    // ---- launch 3: persistent fused chain ----
    ChainParams CP;
    CP.ctxv = ctxv; CP.ctxa = ctxa;
    CP.W_venc = W_venc; CP.W_aenc = W_aenc; CP.W_ca2 = W_ca2;
    CP.v1c = v1c; CP.W_ca3 = W_ca3; CP.W_ih = W_ih;
    CP.b_ih = b_ih; CP.b_hh = b_hh; CP.c0 = c0;
    CP.allctx = allctx; CP.vtmp = vtmp; CP.v2c = v2c; CP.v2ctmp = v2ctmp;
    CP.x2 = x2; CP.gates = gates; CP.gates2 = gates2;
    CP.hsc = hsc; CP.h_out = h_out; CP.c_out = c_out;
    fused_chain<<<128, 128>>>(CP);

    // ---- launch 4: logits on the async core ----
    GemmList L5; L5.n = 1;
    L5.g[0] = mkgrp(hsc, 1024, W_out, 1024, b_out, logits, 20000, 128, 20000, 1024, 0, 0);
    gemm_async_grouped<<<L5.g[0].end, 128>>>(L5);
}

// round 9
// speedup vs baseline: 1.2394x; 1.0528x over previous
#include <cuda_runtime.h>
#include <cstdint>

// ---------------------------------------------------------------------------
// Problem constants
//   B=128, T_V=64, T_A=128, E_V=1024, E_A=512, H=1024, EMB=512, C=512
//   IN=1024, VOCAB=20000
// Output = [logits(128*20000) | h_new(128*1024) | c_new(128*1024)]
// ---------------------------------------------------------------------------

// Scratch offsets (floats)
#define OFF_V2V     0u            // 8192*512
#define OFF_V2A     4194304u      // 16384*512
#define OFF_V1V     12582912u     // 128*512
#define OFF_V1A     12648448u     // 128*512
#define OFF_V1C     12713984u     // 128*512
#define OFF_CTXV    12779520u     // 128*1024
#define OFF_CTXA    12910592u     // 128*512
#define OFF_ALLCTX  12976128u     // 128*2*512
#define OFF_V2C     13107200u     // 256*512
#define OFF_X2      13238272u     // 128*512
#define OFF_GATES   13369344u     // 128*4096
#define OFF_H       13893632u     // 128*1024
#define OFF_VTMP    14024704u     // 128*512
#define OFF_V2CTMP  14090240u     // 256*512
#define OFF_GATES2  14221312u     // 128*4096
#define SCRATCH_FLOATS 14745600u

__device__ float g_scratch[SCRATCH_FLOATS];
__device__ int g_bar[8];   // monotonic barrier counters (never reset; replay-safe)

__device__ __forceinline__ uint32_t f2tf(float f) {
    uint32_t u;
    asm("cvt.rna.tf32.f32 %0, %1;" : "=r"(u) : "f"(f));
    return u;
}

// Grid-wide barrier for a co-resident grid of nblk blocks. Tight spin.
__device__ __forceinline__ void grid_bar(int i, int nblk) {
    __syncthreads();
    if (threadIdx.x == 0) {
        __threadfence();
        int old = atomicAdd(&g_bar[i], 1);
        int goal = (old / nblk + 1) * nblk;
        volatile int* p = &g_bar[i];
        while (*p < goal) { }
        __threadfence();
    }
    __syncthreads();
}

// ---------------------------------------------------------------------------
// Async TF32 core: cp.async 3-stage + XOR-swizzled smem + ldmatrix +
// in-register tf32 cvt (bit-identical numerics to previous rounds).
// Tile 64x64x32, 128 threads. M%64==0, K%32==0, K>=96 effective (all call
// sites have K>=256), lda/ldb%4==0. N ragged OK (B rows clamped; epilogue
// guarded).
// smem layout: sm[12288] uint32 = 48KB exactly:
//   A stages 0..2 at words 0,2048,4096 ; B stages at 6144,8192,10240.
//   Within a stage: row r (0..63) has 32 words; 16B group g stored at
//   physical group g ^ (r & 7)  (conflict-free for cp.async & ldmatrix).
// ---------------------------------------------------------------------------
__device__ __forceinline__ void cp16(uint32_t dst, const float* src) {
    asm volatile("cp.async.ca.shared.global [%0], [%1], 16;"
                 :: "r"(dst), "l"(src));
}
__device__ __forceinline__ void cp_commit() {
    asm volatile("cp.async.commit_group;");
}
__device__ __forceinline__ void ldsm4(uint32_t* r, uint32_t addr) {
    asm volatile("ldmatrix.sync.aligned.m8n8.x4.shared.b16 {%0,%1,%2,%3}, [%4];"
                 : "=r"(r[0]), "=r"(r[1]), "=r"(r[2]), "=r"(r[3]) : "r"(addr));
}

__device__ __forceinline__ void gemm_async_core(
    const float* __restrict__ A, int lda,
    const float* __restrict__ B, int ldb,
    const float* __restrict__ bias,
    float* __restrict__ C, int ldc,
    int N, int K, int accum, int mBase, int nBase,
    uint32_t* sm)
{
    const int tid  = threadIdx.x;
    const int lane = tid & 31;
    const int warp = tid >> 5;
    const int wm = warp >> 1;
    const int wn = warp & 1;
    const int lr = tid >> 3;          // 0..15 row base for loads
    const int lc = tid & 7;           // 16B group
    const int nk = K >> 5;

    const uint32_t smBase = (uint32_t)__cvta_generic_to_shared(sm);

    // ---- cp.async source/dest (swizzled) ----
    const int sg = lc ^ (lr & 7);     // row&7 invariant under +16
    const float* aS[4]; const float* bS[4];
    uint32_t aD[4], bD[4];
#pragma unroll
    for (int i = 0; i < 4; i++) {
        const int row = lr + i * 16;
        aS[i] = A + (size_t)(mBase + row) * lda + (lc << 2);
        int nr = nBase + row;
        if (nr > N - 1) nr = N - 1;
        bS[i] = B + (size_t)nr * ldb + (lc << 2);
        aD[i] = smBase + row * 128 + sg * 16;
        bD[i] = smBase + 24576 + row * 128 + sg * 16;
    }

    auto issue = [&](int kt, int st) {
        const int ko = kt << 5;
        const uint32_t so = (uint32_t)st * 8192u;
#pragma unroll
        for (int i = 0; i < 4; i++) cp16(aD[i] + so, aS[i] + ko);
#pragma unroll
        for (int i = 0; i < 4; i++) cp16(bD[i] + so, bS[i] + ko);
        cp_commit();
    };

    float acc[2][4][4];
#pragma unroll
    for (int i = 0; i < 2; i++)
#pragma unroll
        for (int j = 0; j < 4; j++)
#pragma unroll
            for (int k = 0; k < 4; k++) acc[i][j][k] = 0.f;

    issue(0, 0);
    if (nk > 1) issue(1, 1);
    if (nk > 2) issue(2, 2);

    // ---- ldmatrix addressing (swizzled; xor mask is lane&7) ----
    const int l7 = lane & 7;
    const int q3 = (lane >> 3) & 1;
    const int q4 = (lane >> 4) & 1;
    const uint32_t aAB = smBase + ((wm << 5) + l7 + (q3 << 3)) * 128;
    const uint32_t bAB = smBase + 24576 + ((wn << 5) + l7 + (q4 << 3)) * 128;

    int st = 0;
    for (int kt = 0; kt < nk; kt++) {
        const int rem = nk - 1 - kt;
        if (rem >= 2)      asm volatile("cp.async.wait_group 2;");
        else if (rem == 1) asm volatile("cp.async.wait_group 1;");
        else               asm volatile("cp.async.wait_group 0;");
        __syncthreads();

        const uint32_t sw = (uint32_t)st * 8192u;
#pragma unroll
        for (int kk = 0; kk < 32; kk += 8) {
            const int kk4 = kk >> 2;                 // 0,2,4,6
            uint32_t am[2][4], bm[2][4];
            const uint32_t ag = (uint32_t)((kk4 + q4) ^ l7);
            const uint32_t aaddr = aAB + sw + ag * 16;
            ldsm4(am[0], aaddr);
            ldsm4(am[1], aaddr + 2048);              // +16 rows
            const uint32_t bg = (uint32_t)((kk4 + q3) ^ l7);
            const uint32_t baddr = bAB + sw + bg * 16;
            ldsm4(bm[0], baddr);
            ldsm4(bm[1], baddr + 2048);

            // tf32 rounding on fragments (bit-identical numerics)
#pragma unroll
            for (int im = 0; im < 2; im++)
#pragma unroll
                for (int j = 0; j < 4; j++)
                    am[im][j] = f2tf(__uint_as_float(am[im][j]));
#pragma unroll
            for (int p = 0; p < 2; p++)
#pragma unroll
                for (int j = 0; j < 4; j++)
                    bm[p][j] = f2tf(__uint_as_float(bm[p][j]));

#pragma unroll
            for (int im = 0; im < 2; im++)
#pragma unroll
                for (int jn = 0; jn < 4; jn++) {
                    const uint32_t b0 = bm[jn >> 1][(jn & 1) << 1];
                    const uint32_t b1 = bm[jn >> 1][((jn & 1) << 1) + 1];
                    asm volatile(
                        "mma.sync.aligned.m16n8k8.row.col.f32.tf32.tf32.f32 "
                        "{%0,%1,%2,%3}, {%4,%5,%6,%7}, {%8,%9}, {%0,%1,%2,%3};"
                        : "+f"(acc[im][jn][0]), "+f"(acc[im][jn][1]),
                          "+f"(acc[im][jn][2]), "+f"(acc[im][jn][3])
                        : "r"(am[im][0]), "r"(am[im][1]), "r"(am[im][2]), "r"(am[im][3]),
                          "r"(b0), "r"(b1));
                }
        }

        __syncthreads();
        if (kt + 3 < nk) issue(kt + 3, st);   // (kt+3)%3 == st
        st = (st == 2) ? 0 : st + 1;
    }

#pragma unroll
    for (int im = 0; im < 2; im++) {
        const int m0 = mBase + (wm << 5) + (im << 4) + (lane >> 2);
#pragma unroll
        for (int jn = 0; jn < 4; jn++) {
            const int n0 = nBase + (wn << 5) + (jn << 3) + ((lane & 3) << 1);
#pragma unroll
            for (int half = 0; half < 2; half++) {
                const int m = m0 + half * 8;
                const float v0 = acc[im][jn][half * 2 + 0];
                const float v1 = acc[im][jn][half * 2 + 1];
                if (n0 < N) {
                    float xv = v0 + (bias ? bias[n0] : 0.f);
                    if (accum) C[(size_t)m * ldc + n0] += xv;
                    else       C[(size_t)m * ldc + n0]  = xv;
                }
                if (n0 + 1 < N) {
                    float xv = v1 + (bias ? bias[n0 + 1] : 0.f);
                    if (accum) C[(size_t)m * ldc + n0 + 1] += xv;
                    else       C[(size_t)m * ldc + n0 + 1]  = xv;
                }
            }
        }
    }
}

struct GemmGroup {
    const float* A; const float* B; const float* bias; float* C;
    int lda, ldb, ldc, N, K, accum, nbx, end;
};
struct GemmList { GemmGroup g[8]; int n; };

__global__ void __launch_bounds__(128) gemm_async_grouped(GemmList L)
{
    __shared__ uint32_t sm[12288];   // 48KB exactly

    const int bid = blockIdx.x;
    int gi = 0;
#pragma unroll
    for (int i = 0; i < 8; i++)
        if (i < L.n && bid >= L.g[i].end) gi = i + 1;
    const GemmGroup& G = L.g[gi];
    const int start = gi ? L.g[gi - 1].end : 0;
    const int lb = bid - start;
    const int by = lb / G.nbx;
    const int bx = lb - by * G.nbx;

    gemm_async_core(G.A, G.lda, G.B, G.ldb, G.bias, G.C, G.ldc,
                    G.N, G.K, G.accum, by << 6, bx << 6, sm);
}

// ---------------------------------------------------------------------------
// Both Bahdanau attentions in one launch.
// ---------------------------------------------------------------------------
struct AttParams {
    const float* v1; const float* v2; const float* W3; const float* enc;
    float* ctx; int T, C, E;
};

__global__ void __launch_bounds__(256) attend_both(AttParams P0, AttParams P1)
{
    const AttParams P = (blockIdx.x >> 7) ? P1 : P0;
    const int b = blockIdx.x & 127;
    const int tid = threadIdx.x;
    const int warp = tid >> 5, lane = tid & 31;
    __shared__ float s_sc[128];
    __shared__ float s_inv;

    const int T = P.T, C = P.C, E = P.E;
    const float* v1b = P.v1 + (size_t)b * C;
    const float* v2b = P.v2 + (size_t)b * T * C;

    for (int t = warp; t < T; t += 8) {
        const float* row = v2b + (size_t)t * C;
        float acc = 0.f;
        for (int c = lane; c < C; c += 32)
            acc += tanhf(v1b[c] + row[c]) * P.W3[c];
#pragma unroll
        for (int o = 16; o; o >>= 1) acc += __shfl_xor_sync(0xffffffffu, acc, o);
        if (lane == 0) s_sc[t] = acc;
    }
    __syncthreads();

    if (tid == 0) {
        float m = -1e30f;
        for (int t = 0; t < T; t++) m = fmaxf(m, s_sc[t]);
        float s = 0.f;
        for (int t = 0; t < T; t++) { float e = expf(s_sc[t] - m); s_sc[t] = e; s += e; }
        s_inv = 1.f / s;
    }
    __syncthreads();
    const float inv = s_inv;

    const float* encb = P.enc + (size_t)b * T * E;
    for (int e = tid; e < E; e += 256) {
        float acc = 0.f;
        for (int t = 0; t < T; t++) acc += s_sc[t] * encb[(size_t)t * E + e];
        P.ctx[(size_t)b * E + e] = acc * inv;
    }
}

// ---------------------------------------------------------------------------
// Persistent fused chain with split-K parallelism.
// Grid MUST be 128 blocks x 128 threads (co-resident; tight-spin barriers).
// Reduction scalars alias onto sm (phase-disjoint with GEMM usage).
// ---------------------------------------------------------------------------
struct ChainParams {
    const float* ctxv; const float* ctxa;
    const float* W_venc; const float* W_aenc; const float* W_ca2;
    const float* v1c; const float* W_ca3; const float* W_ih;
    const float* b_ih; const float* b_hh; const float* c0;
    float* allctx; float* vtmp; float* v2c; float* v2ctmp;
    float* x2; float* gates; const float* gates2;
    float* hsc; float* h_out; float* c_out;
};

__global__ void __launch_bounds__(128) fused_chain(ChainParams P)
{
    __shared__ uint32_t sm[12288];   // 48KB; also aliased for P3 reductions
    float* redf = (float*)sm;        // [0..3]=red0, [4..7]=red1, [8]=a0, [9]=a1

    const int bid = blockIdx.x;
    const int tid = threadIdx.x;

    // ---- P1: proj (vis split-K=2 => 32 tasks, aud => 16 tasks) ----
    if (bid < 48) {
        if (bid < 16) {
            gemm_async_core(P.ctxv, 1024, P.W_venc, 1024, nullptr, P.allctx, 1024,
                            512, 512, 0, (bid >> 3) << 6, (bid & 7) << 6, sm);
        } else if (bid < 32) {
            const int t = bid - 16;
            gemm_async_core(P.ctxv + 512, 1024, P.W_venc + 512, 1024, nullptr,
                            P.vtmp, 512,
                            512, 512, 0, (t >> 3) << 6, (t & 7) << 6, sm);
        } else {
            const int t = bid - 32;
            gemm_async_core(P.ctxa, 512, P.W_aenc, 512, nullptr, P.allctx + 512, 1024,
                            512, 512, 0, (t >> 3) << 6, (t & 7) << 6, sm);
        }
    }
    grid_bar(0, 128);

    // ---- P1b: reduce vis partials into allctx ----
    for (int u = bid * 128 + tid; u < 128 * 512; u += 128 * 128) {
        const int b = u >> 9, c = u & 511;
        P.allctx[(size_t)b * 1024 + c] += P.vtmp[u];
    }
    grid_bar(1, 128);

    // ---- P2: v2c[256,512] = allctx @ W_ca2^T, split-K=2 (64 tasks) ----
    if (bid < 64) {
        const int kc = bid >> 5;
        const int t = bid & 31;
        const float* Aa = P.allctx + kc * 256;
        const float* Bb = P.W_ca2 + kc * 256;
        float* Cc = kc ? P.v2ctmp : P.v2c;
        gemm_async_core(Aa, 512, Bb, 512, nullptr, Cc, 512,
                        512, 256, 0, (t >> 3) << 6, (t & 7) << 6, sm);
    }
    grid_bar(2, 128);

    // ---- P3: 2-way softmax + final ctx + x2 = tanh(final_ctx) ----
    {
        const int b = bid;
        const int warp = tid >> 5, lane = tid & 31;
        const float* v1b  = P.v1c + (size_t)b * 512;
        const float* v20  = P.v2c + (size_t)(2 * b) * 512;
        const float* v21  = v20 + 512;
        const float* v20t = P.v2ctmp + (size_t)(2 * b) * 512;
        const float* v21t = v20t + 512;

        float p0 = 0.f, p1 = 0.f;
        for (int c = tid; c < 512; c += 128) {
            const float w = P.W_ca3[c];
            p0 += tanhf(v1b[c] + v20[c] + v20t[c]) * w;
            p1 += tanhf(v1b[c] + v21[c] + v21t[c]) * w;
        }
#pragma unroll
        for (int o = 16; o; o >>= 1) {
            p0 += __shfl_xor_sync(0xffffffffu, p0, o);
            p1 += __shfl_xor_sync(0xffffffffu, p1, o);
        }
        if (lane == 0) { redf[warp] = p0; redf[4 + warp] = p1; }
        __syncthreads();
        if (tid == 0) {
            float s0 = redf[0] + redf[1] + redf[2] + redf[3];
            float s1 = redf[4] + redf[5] + redf[6] + redf[7];
            const float m = fmaxf(s0, s1);
            const float e0 = expf(s0 - m), e1 = expf(s1 - m);
            const float inv = 1.f / (e0 + e1);
            redf[8] = e0 * inv; redf[9] = e1 * inv;
        }
        __syncthreads();
        const float a0 = redf[8], a1 = redf[9];

        const float* ctx0 = P.allctx + (size_t)b * 1024;
        const float* ctx1 = ctx0 + 512;
        float* xb = P.x2 + (size_t)b * 512;
        for (int c = tid; c < 512; c += 128)
            xb[c] = tanhf(a0 * ctx0[c] + a1 * ctx1[c]);
        __syncthreads();   // sm reuse safety before P4 GEMM
    }
    grid_bar(3, 128);

    // ---- P4: gates += x2 @ W_ih[:,512:]^T (128 tasks) ----
    {
        const int by = bid >> 6;
        const int bx = bid & 63;
        gemm_async_core(P.x2, 512, P.W_ih + 512, 1024, nullptr, P.gates, 4096,
                        4096, 512, 1, by << 6, bx << 6, sm);
    }
    grid_bar(4, 128);

    // ---- P5: LSTM pointwise (gates + gates2 + biases) ----
    for (int idx = bid * 128 + tid; idx < 128 * 1024; idx += 128 * 128) {
        const int b = idx >> 10, k = idx & 1023;
        const float* g  = P.gates  + (size_t)b * 4096;
        const float* g2 = P.gates2 + (size_t)b * 4096;
        const float ig = g[k]        + g2[k]        + P.b_ih[k]        + P.b_hh[k];
        const float fg = g[1024 + k] + g2[1024 + k] + P.b_ih[1024 + k] + P.b_hh[1024 + k];
        const float gg = g[2048 + k] + g2[2048 + k] + P.b_ih[2048 + k] + P.b_hh[2048 + k];
        const float og = g[3072 + k] + g2[3072 + k] + P.b_ih[3072 + k] + P.b_hh[3072 + k];

        const float si = 1.f / (1.f + expf(-ig));
        const float sf = 1.f / (1.f + expf(-fg));
        const float so = 1.f / (1.f + expf(-og));
        const float cn = sf * P.c0[idx] + si * tanhf(gg);
        const float hn = so * tanhf(cn);

        P.hsc[idx] = hn;
        P.h_out[idx] = hn;
        P.c_out[idx] = cn;
    }
}

// ---------------------------------------------------------------------------
// Launch
// ---------------------------------------------------------------------------
static inline GemmGroup mkgrp(const float* A, int lda, const float* B, int ldb,
                              const float* bias, float* C, int ldc,
                              int M, int N, int K, int accum, int prevEnd)
{
    GemmGroup g;
    g.A = A; g.B = B; g.bias = bias; g.C = C;
    g.lda = lda; g.ldb = ldb; g.ldc = ldc;
    g.N = N; g.K = K; g.accum = accum;
    g.nbx = (N + 63) / 64;
    g.end = prevEnd + g.nbx * (M / 64);
    return g;
}

extern "C" void kernel_launch(void* const* d_in, const int* in_sizes, int n_in,
                              void* d_out, int out_size)
{
    (void)in_sizes; (void)n_in; (void)out_size;

    float* S = nullptr;
    cudaGetSymbolAddress((void**)&S, g_scratch);

    const float* input  = (const float*)d_in[0];
    const float* enc_v  = (const float*)d_in[1];
    const float* enc_a  = (const float*)d_in[2];
    const float* h0     = (const float*)d_in[3];
    const float* c0     = (const float*)d_in[4];
    const float* W_va1  = (const float*)d_in[5];
    const float* W_va2  = (const float*)d_in[6];
    const float* W_va3  = (const float*)d_in[7];
    const float* W_venc = (const float*)d_in[8];
    const float* W_aa1  = (const float*)d_in[9];
    const float* W_aa2  = (const float*)d_in[10];
    const float* W_aa3  = (const float*)d_in[11];
    const float* W_aenc = (const float*)d_in[12];
    const float* W_ca1  = (const float*)d_in[13];
    const float* W_ca2  = (const float*)d_in[14];
    const float* W_ca3  = (const float*)d_in[15];
    const float* W_ih   = (const float*)d_in[16];
    const float* W_hh   = (const float*)d_in[17];
    const float* b_ih   = (const float*)d_in[18];
    const float* b_hh   = (const float*)d_in[19];
    const float* W_out  = (const float*)d_in[20];
    const float* b_out  = (const float*)d_in[21];

    float* out    = (float*)d_out;
    float* logits = out;
    float* h_out  = out + 128 * 20000;
    float* c_out  = h_out + 128 * 1024;

    float* v2v    = S + OFF_V2V;
    float* v2a    = S + OFF_V2A;
    float* v1v    = S + OFF_V1V;
    float* v1a    = S + OFF_V1A;
    float* v1c    = S + OFF_V1C;
    float* ctxv   = S + OFF_CTXV;
    float* ctxa   = S + OFF_CTXA;
    float* allctx = S + OFF_ALLCTX;
    float* v2c    = S + OFF_V2C;
    float* x2     = S + OFF_X2;
    float* gates  = S + OFF_GATES;
    float* hsc    = S + OFF_H;
    float* vtmp   = S + OFF_VTMP;
    float* v2ctmp = S + OFF_V2CTMP;
    float* gates2 = S + OFF_GATES2;

    // ---- launch 1: everything that depends only on inputs (async core) ----
    GemmList L1; L1.n = 7;
    L1.g[0] = mkgrp(enc_a, 512,  W_aa2, 512,  nullptr, v2a,    512,  16384, 512,  512,  0, 0);
    L1.g[1] = mkgrp(enc_v, 1024, W_va2, 1024, nullptr, v2v,    512,  8192,  512,  1024, 0, L1.g[0].end);
    L1.g[2] = mkgrp(h0,    1024, W_hh,  1024, nullptr, gates,  4096, 128,   4096, 1024, 0, L1.g[1].end);
    L1.g[3] = mkgrp(input, 512,  W_ih,  1024, nullptr, gates2, 4096, 128,   4096, 512,  0, L1.g[2].end);
    L1.g[4] = mkgrp(h0,    1024, W_va1, 1024, nullptr, v1v,    512,  128,   512,  1024, 0, L1.g[3].end);
    L1.g[5] = mkgrp(h0,    1024, W_aa1, 1024, nullptr, v1a,    512,  128,   512,  1024, 0, L1.g[4].end);
    L1.g[6] = mkgrp(h0,    1024, W_ca1, 1024, nullptr, v1c,    512,  128,   512,  1024, 0, L1.g[5].end);
    gemm_async_grouped<<<L1.g[6].end, 128>>>(L1);

    // ---- launch 2: both attentions ----
    AttParams Pv{v1v, v2v, W_va3, enc_v, ctxv, 64, 512, 1024};
    AttParams Pa{v1a, v2a, W_aa3, enc_a, ctxa, 128, 512, 512};
    attend_both<<<256, 256>>>(Pv, Pa);

    // ---- launch 3: persistent fused chain ----
    ChainParams CP;
    CP.ctxv = ctxv; CP.ctxa = ctxa;
    CP.W_venc = W_venc; CP.W_aenc = W_aenc; CP.W_ca2 = W_ca2;
    CP.v1c = v1c; CP.W_ca3 = W_ca3; CP.W_ih = W_ih;
    CP.b_ih = b_ih; CP.b_hh = b_hh; CP.c0 = c0;
    CP.allctx = allctx; CP.vtmp = vtmp; CP.v2c = v2c; CP.v2ctmp = v2ctmp;
    CP.x2 = x2; CP.gates = gates; CP.gates2 = gates2;
    CP.hsc = hsc; CP.h_out = h_out; CP.c_out = c_out;
    fused_chain<<<128, 128>>>(CP);

    // ---- launch 4: logits on the async core ----
    GemmList L5; L5.n = 1;
    L5.g[0] = mkgrp(hsc, 1024, W_out, 1024, b_out, logits, 20000, 128, 20000, 1024, 0, 0);
    gemm_async_grouped<<<L5.g[0].end, 128>>>(L5);
}

// round 10
// speedup vs baseline: 1.2559x; 1.0133x over previous
#include <cuda_runtime.h>
#include <cstdint>

// ---------------------------------------------------------------------------
// Problem constants
//   B=128, T_V=64, T_A=128, E_V=1024, E_A=512, H=1024, EMB=512, C=512
//   IN=1024, VOCAB=20000
// Output = [logits(128*20000) | h_new(128*1024) | c_new(128*1024)]
// ---------------------------------------------------------------------------

// Scratch offsets (floats)
#define OFF_V2V     0u            // 8192*512
#define OFF_V2A     4194304u      // 16384*512
#define OFF_V1V     12582912u     // 128*512
#define OFF_V1A     12648448u     // 128*512
#define OFF_V1C     12713984u     // 128*512
#define OFF_CTXV    12779520u     // 128*1024
#define OFF_CTXA    12910592u     // 128*512
#define OFF_ALLCTX  12976128u     // 128*2*512
#define OFF_V2C     13107200u     // 256*512
#define OFF_X2      13238272u     // 128*512
#define OFF_GATES   13369344u     // 128*4096
#define OFF_H       13893632u     // 128*1024
#define OFF_VTMP    14024704u     // 128*512
#define OFF_V2CTMP  14090240u     // 256*512
#define OFF_GATES2  14221312u     // 128*4096
#define SCRATCH_FLOATS 14745600u

__device__ float g_scratch[SCRATCH_FLOATS];
__device__ int g_bar[8];   // monotonic barrier counters (never reset; replay-safe)

__device__ __forceinline__ uint32_t f2tf(float f) {
    uint32_t u;
    asm("cvt.rna.tf32.f32 %0, %1;" : "=r"(u) : "f"(f));
    return u;
}

// Grid-wide barrier for a co-resident grid of nblk blocks. Tight spin.
__device__ __forceinline__ void grid_bar(int i, int nblk) {
    __syncthreads();
    if (threadIdx.x == 0) {
        __threadfence();
        int old = atomicAdd(&g_bar[i], 1);
        int goal = (old / nblk + 1) * nblk;
        volatile int* p = &g_bar[i];
        while (*p < goal) { }
        __threadfence();
    }
    __syncthreads();
}

// ---------------------------------------------------------------------------
// Async TF32 core: cp.async, 3 smem stages with 2 k-tiles in flight,
// SINGLE barrier per k-tile (write-after-read protection comes from issuing
// into stage (kt+2)%3 == (kt-1)%3, whose readers are ordered by the barrier
// at the top of iteration kt). XOR-swizzled smem + ldmatrix + in-register
// tf32 cvt (bit-identical numerics to previous rounds).
// Tile 64x64x32, 128 threads. M%64==0, K%32==0, lda/ldb%4==0. N ragged OK
// (B rows clamped; epilogue guarded).
// smem layout: sm[12288] uint32 = 48KB:
//   A stages 0..2 at words 0,2048,4096 ; B stages at 6144,8192,10240.
//   Row r has 32 words; 16B group g stored at physical group g ^ (r & 7).
// ---------------------------------------------------------------------------
__device__ __forceinline__ void cp16(uint32_t dst, const float* src) {
    asm volatile("cp.async.ca.shared.global [%0], [%1], 16;"
                 :: "r"(dst), "l"(src));
}
__device__ __forceinline__ void cp_commit() {
    asm volatile("cp.async.commit_group;");
}
__device__ __forceinline__ void ldsm4(uint32_t* r, uint32_t addr) {
    asm volatile("ldmatrix.sync.aligned.m8n8.x4.shared.b16 {%0,%1,%2,%3}, [%4];"
                 : "=r"(r[0]), "=r"(r[1]), "=r"(r[2]), "=r"(r[3]) : "r"(addr));
}

__device__ __forceinline__ void gemm_async_core(
    const float* __restrict__ A, int lda,
    const float* __restrict__ B, int ldb,
    const float* __restrict__ bias,
    float* __restrict__ C, int ldc,
    int N, int K, int accum, int mBase, int nBase,
    uint32_t* sm)
{
    const int tid  = threadIdx.x;
    const int lane = tid & 31;
    const int warp = tid >> 5;
    const int wm = warp >> 1;
    const int wn = warp & 1;
    const int lr = tid >> 3;          // 0..15 row base for loads
    const int lc = tid & 7;           // 16B group
    const int nk = K >> 5;

    const uint32_t smBase = (uint32_t)__cvta_generic_to_shared(sm);

    // ---- cp.async source/dest (swizzled) ----
    const int sg = lc ^ (lr & 7);     // row&7 invariant under +16
    const float* aS[4]; const float* bS[4];
    uint32_t aD[4], bD[4];
#pragma unroll
    for (int i = 0; i < 4; i++) {
        const int row = lr + i * 16;
        aS[i] = A + (size_t)(mBase + row) * lda + (lc << 2);
        int nr = nBase + row;
        if (nr > N - 1) nr = N - 1;
        bS[i] = B + (size_t)nr * ldb + (lc << 2);
        aD[i] = smBase + row * 128 + sg * 16;
        bD[i] = smBase + 24576 + row * 128 + sg * 16;
    }

    auto issue = [&](int kt, int st) {
        const int ko = kt << 5;
        const uint32_t so = (uint32_t)st * 8192u;
#pragma unroll
        for (int i = 0; i < 4; i++) cp16(aD[i] + so, aS[i] + ko);
#pragma unroll
        for (int i = 0; i < 4; i++) cp16(bD[i] + so, bS[i] + ko);
        cp_commit();
    };

    float acc[2][4][4];
#pragma unroll
    for (int i = 0; i < 2; i++)
#pragma unroll
        for (int j = 0; j < 4; j++)
#pragma unroll
            for (int k = 0; k < 4; k++) acc[i][j][k] = 0.f;

    issue(0, 0);
    if (nk > 1) issue(1, 1);

    // ---- ldmatrix addressing (swizzled; xor mask is lane&7) ----
    const int l7 = lane & 7;
    const int q3 = (lane >> 3) & 1;
    const int q4 = (lane >> 4) & 1;
    const uint32_t aAB = smBase + ((wm << 5) + l7 + (q3 << 3)) * 128;
    const uint32_t bAB = smBase + 24576 + ((wn << 5) + l7 + (q4 << 3)) * 128;

    int st = 0;
    for (int kt = 0; kt < nk; kt++) {
        if (kt < nk - 1) asm volatile("cp.async.wait_group 1;");
        else             asm volatile("cp.async.wait_group 0;");
        __syncthreads();

        const uint32_t sw = (uint32_t)st * 8192u;
#pragma unroll
        for (int kk = 0; kk < 32; kk += 8) {
            const int kk4 = kk >> 2;                 // 0,2,4,6
            uint32_t am[2][4], bm[2][4];
            const uint32_t ag = (uint32_t)((kk4 + q4) ^ l7);
            const uint32_t aaddr = aAB + sw + ag * 16;
            ldsm4(am[0], aaddr);
            ldsm4(am[1], aaddr + 2048);              // +16 rows
            const uint32_t bg = (uint32_t)((kk4 + q3) ^ l7);
            const uint32_t baddr = bAB + sw + bg * 16;
            ldsm4(bm[0], baddr);
            ldsm4(bm[1], baddr + 2048);

            // tf32 rounding on fragments (bit-identical numerics)
#pragma unroll
            for (int im = 0; im < 2; im++)
#pragma unroll
                for (int j = 0; j < 4; j++)
                    am[im][j] = f2tf(__uint_as_float(am[im][j]));
#pragma unroll
            for (int p = 0; p < 2; p++)
#pragma unroll
                for (int j = 0; j < 4; j++)
                    bm[p][j] = f2tf(__uint_as_float(bm[p][j]));

#pragma unroll
            for (int im = 0; im < 2; im++)
#pragma unroll
                for (int jn = 0; jn < 4; jn++) {
                    const uint32_t b0 = bm[jn >> 1][(jn & 1) << 1];
                    const uint32_t b1 = bm[jn >> 1][((jn & 1) << 1) + 1];
                    asm volatile(
                        "mma.sync.aligned.m16n8k8.row.col.f32.tf32.tf32.f32 "
                        "{%0,%1,%2,%3}, {%4,%5,%6,%7}, {%8,%9}, {%0,%1,%2,%3};"
                        : "+f"(acc[im][jn][0]), "+f"(acc[im][jn][1]),
                          "+f"(acc[im][jn][2]), "+f"(acc[im][jn][3])
                        : "r"(am[im][0]), "r"(am[im][1]), "r"(am[im][2]), "r"(am[im][3]),
                          "r"(b0), "r"(b1));
                }
        }

        // Issue next prefetch into stage (kt+2)%3 == (kt-1)%3 — its readers
        // finished before the barrier at the TOP of this iteration, so no
        // second barrier is required.
        if (kt + 2 < nk) issue(kt + 2, (st == 0) ? 2 : st - 1);
        st = (st == 2) ? 0 : st + 1;
    }

#pragma unroll
    for (int im = 0; im < 2; im++) {
        const int m0 = mBase + (wm << 5) + (im << 4) + (lane >> 2);
#pragma unroll
        for (int jn = 0; jn < 4; jn++) {
            const int n0 = nBase + (wn << 5) + (jn << 3) + ((lane & 3) << 1);
#pragma unroll
            for (int half = 0; half < 2; half++) {
                const int m = m0 + half * 8;
                const float v0 = acc[im][jn][half * 2 + 0];
                const float v1 = acc[im][jn][half * 2 + 1];
                if (n0 < N) {
                    float xv = v0 + (bias ? bias[n0] : 0.f);
                    if (accum) C[(size_t)m * ldc + n0] += xv;
                    else       C[(size_t)m * ldc + n0]  = xv;
                }
                if (n0 + 1 < N) {
                    float xv = v1 + (bias ? bias[n0 + 1] : 0.f);
                    if (accum) C[(size_t)m * ldc + n0 + 1] += xv;
                    else       C[(size_t)m * ldc + n0 + 1]  = xv;
                }
            }
        }
    }
}

struct GemmGroup {
    const float* A; const float* B; const float* bias; float* C;
    int lda, ldb, ldc, N, K, accum, nbx, end;
};
struct GemmList { GemmGroup g[8]; int n; };

__global__ void __launch_bounds__(128) gemm_async_grouped(GemmList L)
{
    __shared__ uint32_t sm[12288];   // 48KB exactly

    const int bid = blockIdx.x;
    int gi = 0;
#pragma unroll
    for (int i = 0; i < 8; i++)
        if (i < L.n && bid >= L.g[i].end) gi = i + 1;
    const GemmGroup& G = L.g[gi];
    const int start = gi ? L.g[gi - 1].end : 0;
    const int lb = bid - start;
    const int by = lb / G.nbx;
    const int bx = lb - by * G.nbx;

    gemm_async_core(G.A, G.lda, G.B, G.ldb, G.bias, G.C, G.ldc,
                    G.N, G.K, G.accum, by << 6, bx << 6, sm);
}

// ---------------------------------------------------------------------------
// Both Bahdanau attentions in one launch.
// ---------------------------------------------------------------------------
struct AttParams {
    const float* v1; const float* v2; const float* W3; const float* enc;
    float* ctx; int T, C, E;
};

__global__ void __launch_bounds__(256) attend_both(AttParams P0, AttParams P1)
{
    const AttParams P = (blockIdx.x >> 7) ? P1 : P0;
    const int b = blockIdx.x & 127;
    const int tid = threadIdx.x;
    const int warp = tid >> 5, lane = tid & 31;
    __shared__ float s_sc[128];
    __shared__ float s_inv;

    const int T = P.T, C = P.C, E = P.E;
    const float* v1b = P.v1 + (size_t)b * C;
    const float* v2b = P.v2 + (size_t)b * T * C;

    for (int t = warp; t < T; t += 8) {
        const float* row = v2b + (size_t)t * C;
        float acc = 0.f;
        for (int c = lane; c < C; c += 32)
            acc += tanhf(v1b[c] + row[c]) * P.W3[c];
#pragma unroll
        for (int o = 16; o; o >>= 1) acc += __shfl_xor_sync(0xffffffffu, acc, o);
        if (lane == 0) s_sc[t] = acc;
    }
    __syncthreads();

    if (tid == 0) {
        float m = -1e30f;
        for (int t = 0; t < T; t++) m = fmaxf(m, s_sc[t]);
        float s = 0.f;
        for (int t = 0; t < T; t++) { float e = expf(s_sc[t] - m); s_sc[t] = e; s += e; }
        s_inv = 1.f / s;
    }
    __syncthreads();
    const float inv = s_inv;

    const float* encb = P.enc + (size_t)b * T * E;
    for (int e = tid; e < E; e += 256) {
        float acc = 0.f;
        for (int t = 0; t < T; t++) acc += s_sc[t] * encb[(size_t)t * E + e];
        P.ctx[(size_t)b * E + e] = acc * inv;
    }
}

// ---------------------------------------------------------------------------
// Persistent fused chain with split-K parallelism.
// Grid MUST be 128 blocks x 128 threads (co-resident; tight-spin barriers).
// Reduction scalars alias onto sm (phase-disjoint with GEMM usage).
// ---------------------------------------------------------------------------
struct ChainParams {
    const float* ctxv; const float* ctxa;
    const float* W_venc; const float* W_aenc; const float* W_ca2;
    const float* v1c; const float* W_ca3; const float* W_ih;
    const float* b_ih; const float* b_hh; const float* c0;
    float* allctx; float* vtmp; float* v2c; float* v2ctmp;
    float* x2; float* gates; const float* gates2;
    float* hsc; float* h_out; float* c_out;
};

__global__ void __launch_bounds__(128) fused_chain(ChainParams P)
{
    __shared__ uint32_t sm[12288];   // 48KB; also aliased for P3 reductions
    float* redf = (float*)sm;        // [0..3]=red0, [4..7]=red1, [8]=a0, [9]=a1

    const int bid = blockIdx.x;
    const int tid = threadIdx.x;

    // ---- P1: proj (vis split-K=2 => 32 tasks, aud => 16 tasks) ----
    if (bid < 48) {
        if (bid < 16) {
            gemm_async_core(P.ctxv, 1024, P.W_venc, 1024, nullptr, P.allctx, 1024,
                            512, 512, 0, (bid >> 3) << 6, (bid & 7) << 6, sm);
        } else if (bid < 32) {
            const int t = bid - 16;
            gemm_async_core(P.ctxv + 512, 1024, P.W_venc + 512, 1024, nullptr,
                            P.vtmp, 512,
                            512, 512, 0, (t >> 3) << 6, (t & 7) << 6, sm);
        } else {
            const int t = bid - 32;
            gemm_async_core(P.ctxa, 512, P.W_aenc, 512, nullptr, P.allctx + 512, 1024,
                            512, 512, 0, (t >> 3) << 6, (t & 7) << 6, sm);
        }
    }
    grid_bar(0, 128);

    // ---- P1b: reduce vis partials into allctx ----
    for (int u = bid * 128 + tid; u < 128 * 512; u += 128 * 128) {
        const int b = u >> 9, c = u & 511;
        P.allctx[(size_t)b * 1024 + c] += P.vtmp[u];
    }
    grid_bar(1, 128);

    // ---- P2: v2c[256,512] = allctx @ W_ca2^T, split-K=2 (64 tasks) ----
    if (bid < 64) {
        const int kc = bid >> 5;
        const int t = bid & 31;
        const float* Aa = P.allctx + kc * 256;
        const float* Bb = P.W_ca2 + kc * 256;
        float* Cc = kc ? P.v2ctmp : P.v2c;
        gemm_async_core(Aa, 512, Bb, 512, nullptr, Cc, 512,
                        512, 256, 0, (t >> 3) << 6, (t & 7) << 6, sm);
    }
    grid_bar(2, 128);

    // ---- P3: 2-way softmax + final ctx + x2 = tanh(final_ctx) ----
    {
        const int b = bid;
        const int warp = tid >> 5, lane = tid & 31;
        const float* v1b  = P.v1c + (size_t)b * 512;
        const float* v20  = P.v2c + (size_t)(2 * b) * 512;
        const float* v21  = v20 + 512;
        const float* v20t = P.v2ctmp + (size_t)(2 * b) * 512;
        const float* v21t = v20t + 512;

        float p0 = 0.f, p1 = 0.f;
        for (int c = tid; c < 512; c += 128) {
            const float w = P.W_ca3[c];
            p0 += tanhf(v1b[c] + v20[c] + v20t[c]) * w;
            p1 += tanhf(v1b[c] + v21[c] + v21t[c]) * w;
        }
#pragma unroll
        for (int o = 16; o; o >>= 1) {
            p0 += __shfl_xor_sync(0xffffffffu, p0, o);
            p1 += __shfl_xor_sync(0xffffffffu, p1, o);
        }
        if (lane == 0) { redf[warp] = p0; redf[4 + warp] = p1; }
        __syncthreads();
        if (tid == 0) {
            float s0 = redf[0] + redf[1] + redf[2] + redf[3];
            float s1 = redf[4] + redf[5] + redf[6] + redf[7];
            const float m = fmaxf(s0, s1);
            const float e0 = expf(s0 - m), e1 = expf(s1 - m);
            const float inv = 1.f / (e0 + e1);
            redf[8] = e0 * inv; redf[9] = e1 * inv;
        }
        __syncthreads();
        const float a0 = redf[8], a1 = redf[9];

        const float* ctx0 = P.allctx + (size_t)b * 1024;
        const float* ctx1 = ctx0 + 512;
        float* xb = P.x2 + (size_t)b * 512;
        for (int c = tid; c < 512; c += 128)
            xb[c] = tanhf(a0 * ctx0[c] + a1 * ctx1[c]);
        __syncthreads();   // sm reuse safety before P4 GEMM
    }
    grid_bar(3, 128);

    // ---- P4: gates += x2 @ W_ih[:,512:]^T (128 tasks) ----
    {
        const int by = bid >> 6;
        const int bx = bid & 63;
        gemm_async_core(P.x2, 512, P.W_ih + 512, 1024, nullptr, P.gates, 4096,
                        4096, 512, 1, by << 6, bx << 6, sm);
    }
    grid_bar(4, 128);

    // ---- P5: LSTM pointwise (gates + gates2 + biases) ----
    for (int idx = bid * 128 + tid; idx < 128 * 1024; idx += 128 * 128) {
        const int b = idx >> 10, k = idx & 1023;
        const float* g  = P.gates  + (size_t)b * 4096;
        const float* g2 = P.gates2 + (size_t)b * 4096;
        const float ig = g[k]        + g2[k]        + P.b_ih[k]        + P.b_hh[k];
        const float fg = g[1024 + k] + g2[1024 + k] + P.b_ih[1024 + k] + P.b_hh[1024 + k];
        const float gg = g[2048 + k] + g2[2048 + k] + P.b_ih[2048 + k] + P.b_hh[2048 + k];
        const float og = g[3072 + k] + g2[3072 + k] + P.b_ih[3072 + k] + P.b_hh[3072 + k];

        const float si = 1.f / (1.f + expf(-ig));
        const float sf = 1.f / (1.f + expf(-fg));
        const float so = 1.f / (1.f + expf(-og));
        const float cn = sf * P.c0[idx] + si * tanhf(gg);
        const float hn = so * tanhf(cn);

        P.hsc[idx] = hn;
        P.h_out[idx] = hn;
        P.c_out[idx] = cn;
    }
}

// ---------------------------------------------------------------------------
// Launch
// ---------------------------------------------------------------------------
static inline GemmGroup mkgrp(const float* A, int lda, const float* B, int ldb,
                              const float* bias, float* C, int ldc,
                              int M, int N, int K, int accum, int prevEnd)
{
    GemmGroup g;
    g.A = A; g.B = B; g.bias = bias; g.C = C;
    g.lda = lda; g.ldb = ldb; g.ldc = ldc;
    g.N = N; g.K = K; g.accum = accum;
    g.nbx = (N + 63) / 64;
    g.end = prevEnd + g.nbx * (M / 64);
    return g;
}

extern "C" void kernel_launch(void* const* d_in, const int* in_sizes, int n_in,
                              void* d_out, int out_size)
{
    (void)in_sizes; (void)n_in; (void)out_size;

    float* S = nullptr;
    cudaGetSymbolAddress((void**)&S, g_scratch);

    const float* input  = (const float*)d_in[0];
    const float* enc_v  = (const float*)d_in[1];
    const float* enc_a  = (const float*)d_in[2];
    const float* h0     = (const float*)d_in[3];
    const float* c0     = (const float*)d_in[4];
    const float* W_va1  = (const float*)d_in[5];
    const float* W_va2  = (const float*)d_in[6];
    const float* W_va3  = (const float*)d_in[7];
    const float* W_venc = (const float*)d_in[8];
    const float* W_aa1  = (const float*)d_in[9];
    const float* W_aa2  = (const float*)d_in[10];
    const float* W_aa3  = (const float*)d_in[11];
    const float* W_aenc = (const float*)d_in[12];
    const float* W_ca1  = (const float*)d_in[13];
    const float* W_ca2  = (const float*)d_in[14];
    const float* W_ca3  = (const float*)d_in[15];
    const float* W_ih   = (const float*)d_in[16];
    const float* W_hh   = (const float*)d_in[17];
    const float* b_ih   = (const float*)d_in[18];
    const float* b_hh   = (const float*)d_in[19];
    const float* W_out  = (const float*)d_in[20];
    const float* b_out  = (const float*)d_in[21];

    float* out    = (float*)d_out;
    float* logits = out;
    float* h_out  = out + 128 * 20000;
    float* c_out  = h_out + 128 * 1024;

    float* v2v    = S + OFF_V2V;
    float* v2a    = S + OFF_V2A;
    float* v1v    = S + OFF_V1V;
    float* v1a    = S + OFF_V1A;
    float* v1c    = S + OFF_V1C;
    float* ctxv   = S + OFF_CTXV;
    float* ctxa   = S + OFF_CTXA;
    float* allctx = S + OFF_ALLCTX;
    float* v2c    = S + OFF_V2C;
    float* x2     = S + OFF_X2;
    float* gates  = S + OFF_GATES;
    float* hsc    = S + OFF_H;
    float* vtmp   = S + OFF_VTMP;
    float* v2ctmp = S + OFF_V2CTMP;
    float* gates2 = S + OFF_GATES2;

    // ---- launch 1: everything that depends only on inputs (async core) ----
    GemmList L1; L1.n = 7;
    L1.g[0] = mkgrp(enc_a, 512,  W_aa2, 512,  nullptr, v2a,    512,  16384, 512,  512,  0, 0);
    L1.g[1] = mkgrp(enc_v, 1024, W_va2, 1024, nullptr, v2v,    512,  8192,  512,  1024, 0, L1.g[0].end);
    L1.g[2] = mkgrp(h0,    1024, W_hh,  1024, nullptr, gates,  4096, 128,   4096, 1024, 0, L1.g[1].end);
    L1.g[3] = mkgrp(input, 512,  W_ih,  1024, nullptr, gates2, 4096, 128,   4096, 512,  0, L1.g[2].end);
    L1.g[4] = mkgrp(h0,    1024, W_va1, 1024, nullptr, v1v,    512,  128,   512,  1024, 0, L1.g[3].end);
    L1.g[5] = mkgrp(h0,    1024, W_aa1, 1024, nullptr, v1a,    512,  128,   512,  1024, 0, L1.g[4].end);
    L1.g[6] = mkgrp(h0,    1024, W_ca1, 1024, nullptr, v1c,    512,  128,   512,  1024, 0, L1.g[5].end);
    gemm_async_grouped<<<L1.g[6].end, 128>>>(L1);

    // ---- launch 2: both attentions ----
    AttParams Pv{v1v, v2v, W_va3, enc_v, ctxv, 64, 512, 1024};
    AttParams Pa{v1a, v2a, W_aa3, enc_a, ctxa, 128, 512, 512};
    attend_both<<<256, 256>>>(Pv, Pa);

    // ---- launch 3: persistent fused chain ----
    ChainParams CP;
    CP.ctxv = ctxv; CP.ctxa = ctxa;
    CP.W_venc = W_venc; CP.W_aenc = W_aenc; CP.W_ca2 = W_ca2;
    CP.v1c = v1c; CP.W_ca3 = W_ca3; CP.W_ih = W_ih;
    CP.b_ih = b_ih; CP.b_hh = b_hh; CP.c0 = c0;
    CP.allctx = allctx; CP.vtmp = vtmp; CP.v2c = v2c; CP.v2ctmp = v2ctmp;
    CP.x2 = x2; CP.gates = gates; CP.gates2 = gates2;
    CP.hsc = hsc; CP.h_out = h_out; CP.c_out = c_out;
    fused_chain<<<128, 128>>>(CP);

    // ---- launch 4: logits on the async core ----
    GemmList L5; L5.n = 1;
    L5.g[0] = mkgrp(hsc, 1024, W_out, 1024, b_out, logits, 20000, 128, 20000, 1024, 0, 0);
    gemm_async_grouped<<<L5.g[0].end, 128>>>(L5);
}

// round 11
// speedup vs baseline: 1.3137x; 1.0460x over previous
#include <cuda_runtime.h>
#include <cstdint>

// ---------------------------------------------------------------------------
// Problem constants
//   B=128, T_V=64, T_A=128, E_V=1024, E_A=512, H=1024, EMB=512, C=512
//   IN=1024, VOCAB=20000
// Output = [logits(128*20000) | h_new(128*1024) | c_new(128*1024)]
// ---------------------------------------------------------------------------

// Scratch offsets (floats)
#define OFF_V2V     0u            // 8192*512
#define OFF_V2A     4194304u      // 16384*512
#define OFF_V1V     12582912u     // 128*512
#define OFF_V1A     12648448u     // 128*512
#define OFF_V1C     12713984u     // 128*512
#define OFF_CTXV    12779520u     // 128*1024
#define OFF_CTXA    12910592u     // 128*512
#define OFF_ALLCTX  12976128u     // 128*2*512
#define OFF_V2C     13107200u     // 256*512
#define OFF_X2      13238272u     // 128*512
#define OFF_GATES   13369344u     // 128*4096
#define OFF_H       13893632u     // 128*1024
#define OFF_VTMP    14024704u     // 128*512
#define OFF_V2CTMP  14090240u     // 256*512
#define OFF_GATES2  14221312u     // 128*4096
#define SCRATCH_FLOATS 14745600u

__device__ float g_scratch[SCRATCH_FLOATS];
__device__ int g_bar[8];   // monotonic barrier counters (never reset; replay-safe)

__device__ __forceinline__ uint32_t f2tf(float f) {
    uint32_t u;
    asm("cvt.rna.tf32.f32 %0, %1;" : "=r"(u) : "f"(f));
    return u;
}

// Grid-wide barrier for a co-resident grid of nblk blocks. Tight spin.
__device__ __forceinline__ void grid_bar(int i, int nblk) {
    __syncthreads();
    if (threadIdx.x == 0) {
        __threadfence();
        int old = atomicAdd(&g_bar[i], 1);
        int goal = (old / nblk + 1) * nblk;
        volatile int* p = &g_bar[i];
        while (*p < goal) { }
        __threadfence();
    }
    __syncthreads();
}

// ---------------------------------------------------------------------------
// Async TF32 core, FAT tile: 128(M) x 64(N) x 32(K), 128 threads, 4 warps
// as 2x2, warp tile 64x32 (16 MMAs per kk-step -> better MMA issue fraction).
// cp.async 2-stage + XOR-swizzled smem + ldmatrix + in-register tf32 cvt
// (bit-identical numerics to previous rounds: cvt.rna per fragment, same
// k-step accumulation order per output element).
// Requirements: M % 128 == 0, K % 32 == 0, lda/ldb % 4 == 0. N ragged OK
// (B rows clamped; epilogue guarded).
// smem sm[12288] uint32 = 48KB:
//   A stage0 @ byte 0, A stage1 @ 16384 (128 rows x 128B each)
//   B stage0 @ 32768, B stage1 @ 40960 (64 rows x 128B each)
//   Row r: 16B group g stored at physical group g ^ (r & 7).
// ---------------------------------------------------------------------------
__device__ __forceinline__ void cp16(uint32_t dst, const float* src) {
    asm volatile("cp.async.ca.shared.global [%0], [%1], 16;"
                 :: "r"(dst), "l"(src));
}
__device__ __forceinline__ void cp_commit() {
    asm volatile("cp.async.commit_group;");
}
__device__ __forceinline__ void ldsm4(uint32_t* r, uint32_t addr) {
    asm volatile("ldmatrix.sync.aligned.m8n8.x4.shared.b16 {%0,%1,%2,%3}, [%4];"
                 : "=r"(r[0]), "=r"(r[1]), "=r"(r[2]), "=r"(r[3]) : "r"(addr));
}

__device__ __forceinline__ void gemm_async_core(
    const float* __restrict__ A, int lda,
    const float* __restrict__ B, int ldb,
    const float* __restrict__ bias,
    float* __restrict__ C, int ldc,
    int N, int K, int accum, int mBase, int nBase,
    uint32_t* sm)
{
    const int tid  = threadIdx.x;
    const int lane = tid & 31;
    const int warp = tid >> 5;
    const int wm = warp >> 1;         // 0..1 -> 64-row slab
    const int wn = warp & 1;          // 0..1 -> 32-col slab
    const int lr = tid >> 3;          // 0..15 row base for loads
    const int lc = tid & 7;           // 16B group
    const int nk = K >> 5;

    const uint32_t smBase = (uint32_t)__cvta_generic_to_shared(sm);

    // ---- cp.async source/dest (swizzled; row&7 invariant under +16) ----
    const int sg = lc ^ (lr & 7);
    const float* aS0 = A + (size_t)(mBase + lr) * lda + (lc << 2);
    const size_t strideA16 = (size_t)16 * lda;
    const float* bS[4];
#pragma unroll
    for (int i = 0; i < 4; i++) {
        int nr = nBase + lr + i * 16;
        if (nr > N - 1) nr = N - 1;
        bS[i] = B + (size_t)nr * ldb + (lc << 2);
    }
    const uint32_t aD = smBase + lr * 128 + sg * 16;
    const uint32_t bD = smBase + 32768 + lr * 128 + sg * 16;

    auto issue = [&](int kt, int st) {
        const int ko = kt << 5;
        const uint32_t soA = st ? 16384u : 0u;
        const uint32_t soB = st ? 8192u : 0u;
#pragma unroll
        for (int i = 0; i < 8; i++)
            cp16(aD + (uint32_t)i * 2048u + soA, aS0 + (size_t)i * strideA16 + ko);
#pragma unroll
        for (int i = 0; i < 4; i++)
            cp16(bD + (uint32_t)i * 2048u + soB, bS[i] + ko);
        cp_commit();
    };

    float acc[4][4][4];
#pragma unroll
    for (int i = 0; i < 4; i++)
#pragma unroll
        for (int j = 0; j < 4; j++)
#pragma unroll
            for (int k = 0; k < 4; k++) acc[i][j][k] = 0.f;

    issue(0, 0);
    if (nk > 1) issue(1, 1);

    // ---- ldmatrix addressing (swizzled; xor mask is lane&7) ----
    const int l7 = lane & 7;
    const int q3 = (lane >> 3) & 1;
    const int q4 = (lane >> 4) & 1;
    const uint32_t aAB = smBase + ((wm << 6) + l7 + (q3 << 3)) * 128;
    const uint32_t bAB = smBase + 32768 + ((wn << 5) + l7 + (q4 << 3)) * 128;

    for (int kt = 0; kt < nk; kt++) {
        if (kt < nk - 1) asm volatile("cp.async.wait_group 1;");
        else             asm volatile("cp.async.wait_group 0;");
        __syncthreads();

        const int st = kt & 1;
        const uint32_t swA = st ? 16384u : 0u;
        const uint32_t swB = st ? 8192u : 0u;
#pragma unroll
        for (int kk = 0; kk < 32; kk += 8) {
            const int kk4 = kk >> 2;                 // 0,2,4,6
            uint32_t am[4][4], bm[2][4];
            const uint32_t ag = (uint32_t)((kk4 + q4) ^ l7);
            const uint32_t aaddr = aAB + swA + ag * 16;
            ldsm4(am[0], aaddr);
            ldsm4(am[1], aaddr + 2048);              // +16 rows
            ldsm4(am[2], aaddr + 4096);
            ldsm4(am[3], aaddr + 6144);
            const uint32_t bg = (uint32_t)((kk4 + q3) ^ l7);
            const uint32_t baddr = bAB + swB + bg * 16;
            ldsm4(bm[0], baddr);
            ldsm4(bm[1], baddr + 2048);

            // tf32 rounding on fragments (bit-identical numerics)
#pragma unroll
            for (int im = 0; im < 4; im++)
#pragma unroll
                for (int j = 0; j < 4; j++)
                    am[im][j] = f2tf(__uint_as_float(am[im][j]));
#pragma unroll
            for (int p = 0; p < 2; p++)
#pragma unroll
                for (int j = 0; j < 4; j++)
                    bm[p][j] = f2tf(__uint_as_float(bm[p][j]));

#pragma unroll
            for (int im = 0; im < 4; im++)
#pragma unroll
                for (int jn = 0; jn < 4; jn++) {
                    const uint32_t b0 = bm[jn >> 1][(jn & 1) << 1];
                    const uint32_t b1 = bm[jn >> 1][((jn & 1) << 1) + 1];
                    asm volatile(
                        "mma.sync.aligned.m16n8k8.row.col.f32.tf32.tf32.f32 "
                        "{%0,%1,%2,%3}, {%4,%5,%6,%7}, {%8,%9}, {%0,%1,%2,%3};"
                        : "+f"(acc[im][jn][0]), "+f"(acc[im][jn][1]),
                          "+f"(acc[im][jn][2]), "+f"(acc[im][jn][3])
                        : "r"(am[im][0]), "r"(am[im][1]), "r"(am[im][2]), "r"(am[im][3]),
                          "r"(b0), "r"(b1));
                }
        }

        __syncthreads();
        if (kt + 2 < nk) issue(kt + 2, kt & 1);
    }

#pragma unroll
    for (int im = 0; im < 4; im++) {
        const int m0 = mBase + (wm << 6) + (im << 4) + (lane >> 2);
#pragma unroll
        for (int jn = 0; jn < 4; jn++) {
            const int n0 = nBase + (wn << 5) + (jn << 3) + ((lane & 3) << 1);
#pragma unroll
            for (int half = 0; half < 2; half++) {
                const int m = m0 + half * 8;
                const float v0 = acc[im][jn][half * 2 + 0];
                const float v1 = acc[im][jn][half * 2 + 1];
                if (n0 < N) {
                    float xv = v0 + (bias ? bias[n0] : 0.f);
                    if (accum) C[(size_t)m * ldc + n0] += xv;
                    else       C[(size_t)m * ldc + n0]  = xv;
                }
                if (n0 + 1 < N) {
                    float xv = v1 + (bias ? bias[n0 + 1] : 0.f);
                    if (accum) C[(size_t)m * ldc + n0 + 1] += xv;
                    else       C[(size_t)m * ldc + n0 + 1]  = xv;
                }
            }
        }
    }
}

struct GemmGroup {
    const float* A; const float* B; const float* bias; float* C;
    int lda, ldb, ldc, N, K, accum, nbx, end;
};
struct GemmList { GemmGroup g[8]; int n; };

__global__ void __launch_bounds__(128) gemm_async_grouped(GemmList L)
{
    __shared__ uint32_t sm[12288];   // 48KB exactly

    const int bid = blockIdx.x;
    int gi = 0;
#pragma unroll
    for (int i = 0; i < 8; i++)
        if (i < L.n && bid >= L.g[i].end) gi = i + 1;
    const GemmGroup& G = L.g[gi];
    const int start = gi ? L.g[gi - 1].end : 0;
    const int lb = bid - start;
    const int by = lb / G.nbx;
    const int bx = lb - by * G.nbx;

    gemm_async_core(G.A, G.lda, G.B, G.ldb, G.bias, G.C, G.ldc,
                    G.N, G.K, G.accum, by << 7, bx << 6, sm);
}

// ---------------------------------------------------------------------------
// Both Bahdanau attentions in one launch.
// ---------------------------------------------------------------------------
struct AttParams {
    const float* v1; const float* v2; const float* W3; const float* enc;
    float* ctx; int T, C, E;
};

__global__ void __launch_bounds__(256) attend_both(AttParams P0, AttParams P1)
{
    const AttParams P = (blockIdx.x >> 7) ? P1 : P0;
    const int b = blockIdx.x & 127;
    const int tid = threadIdx.x;
    const int warp = tid >> 5, lane = tid & 31;
    __shared__ float s_sc[128];
    __shared__ float s_inv;

    const int T = P.T, C = P.C, E = P.E;
    const float* v1b = P.v1 + (size_t)b * C;
    const float* v2b = P.v2 + (size_t)b * T * C;

    for (int t = warp; t < T; t += 8) {
        const float* row = v2b + (size_t)t * C;
        float acc = 0.f;
        for (int c = lane; c < C; c += 32)
            acc += tanhf(v1b[c] + row[c]) * P.W3[c];
#pragma unroll
        for (int o = 16; o; o >>= 1) acc += __shfl_xor_sync(0xffffffffu, acc, o);
        if (lane == 0) s_sc[t] = acc;
    }
    __syncthreads();

    if (tid == 0) {
        float m = -1e30f;
        for (int t = 0; t < T; t++) m = fmaxf(m, s_sc[t]);
        float s = 0.f;
        for (int t = 0; t < T; t++) { float e = expf(s_sc[t] - m); s_sc[t] = e; s += e; }
        s_inv = 1.f / s;
    }
    __syncthreads();
    const float inv = s_inv;

    const float* encb = P.enc + (size_t)b * T * E;
    for (int e = tid; e < E; e += 256) {
        float acc = 0.f;
        for (int t = 0; t < T; t++) acc += s_sc[t] * encb[(size_t)t * E + e];
        P.ctx[(size_t)b * E + e] = acc * inv;
    }
}

// ---------------------------------------------------------------------------
// Persistent fused chain with split-K parallelism (128x64 tile tasks).
// Grid MUST be 128 blocks x 128 threads (co-resident; tight-spin barriers).
// ---------------------------------------------------------------------------
struct ChainParams {
    const float* ctxv; const float* ctxa;
    const float* W_venc; const float* W_aenc; const float* W_ca2;
    const float* v1c; const float* W_ca3; const float* W_ih;
    const float* b_ih; const float* b_hh; const float* c0;
    float* allctx; float* vtmp; float* v2c; float* v2ctmp;
    float* x2; float* gates; const float* gates2;
    float* hsc; float* h_out; float* c_out;
};

__global__ void __launch_bounds__(128) fused_chain(ChainParams P)
{
    __shared__ uint32_t sm[12288];   // 48KB; aliased for P3 reductions
    float* redf = (float*)sm;        // [0..3]=red0, [4..7]=red1, [8]=a0, [9]=a1

    const int bid = blockIdx.x;
    const int tid = threadIdx.x;

    // ---- P1: proj, M=128 tiles (vis split-K=2 => 16 tasks, aud => 8) ----
    if (bid < 24) {
        if (bid < 8) {
            gemm_async_core(P.ctxv, 1024, P.W_venc, 1024, nullptr, P.allctx, 1024,
                            512, 512, 0, 0, bid << 6, sm);
        } else if (bid < 16) {
            const int t = bid - 8;
            gemm_async_core(P.ctxv + 512, 1024, P.W_venc + 512, 1024, nullptr,
                            P.vtmp, 512, 512, 512, 0, 0, t << 6, sm);
        } else {
            const int t = bid - 16;
            gemm_async_core(P.ctxa, 512, P.W_aenc, 512, nullptr, P.allctx + 512, 1024,
                            512, 512, 0, 0, t << 6, sm);
        }
    }
    grid_bar(0, 128);

    // ---- P1b: reduce vis partials into allctx ----
    for (int u = bid * 128 + tid; u < 128 * 512; u += 128 * 128) {
        const int b = u >> 9, c = u & 511;
        P.allctx[(size_t)b * 1024 + c] += P.vtmp[u];
    }
    grid_bar(1, 128);

    // ---- P2: v2c[256,512] = allctx @ W_ca2^T, split-K=2 (32 tasks) ----
    if (bid < 32) {
        const int kc = bid >> 4;
        const int t = bid & 15;
        const float* Aa = P.allctx + kc * 256;
        const float* Bb = P.W_ca2 + kc * 256;
        float* Cc = kc ? P.v2ctmp : P.v2c;
        gemm_async_core(Aa, 512, Bb, 512, nullptr, Cc, 512,
                        512, 256, 0, (t >> 3) << 7, (t & 7) << 6, sm);
    }
    grid_bar(2, 128);

    // ---- P3: 2-way softmax + final ctx + x2 = tanh(final_ctx) ----
    {
        const int b = bid;
        const int warp = tid >> 5, lane = tid & 31;
        const float* v1b  = P.v1c + (size_t)b * 512;
        const float* v20  = P.v2c + (size_t)(2 * b) * 512;
        const float* v21  = v20 + 512;
        const float* v20t = P.v2ctmp + (size_t)(2 * b) * 512;
        const float* v21t = v20t + 512;

        float p0 = 0.f, p1 = 0.f;
        for (int c = tid; c < 512; c += 128) {
            const float w = P.W_ca3[c];
            p0 += tanhf(v1b[c] + v20[c] + v20t[c]) * w;
            p1 += tanhf(v1b[c] + v21[c] + v21t[c]) * w;
        }
#pragma unroll
        for (int o = 16; o; o >>= 1) {
            p0 += __shfl_xor_sync(0xffffffffu, p0, o);
            p1 += __shfl_xor_sync(0xffffffffu, p1, o);
        }
        if (lane == 0) { redf[warp] = p0; redf[4 + warp] = p1; }
        __syncthreads();
        if (tid == 0) {
            float s0 = redf[0] + redf[1] + redf[2] + redf[3];
            float s1 = redf[4] + redf[5] + redf[6] + redf[7];
            const float m = fmaxf(s0, s1);
            const float e0 = expf(s0 - m), e1 = expf(s1 - m);
            const float inv = 1.f / (e0 + e1);
            redf[8] = e0 * inv; redf[9] = e1 * inv;
        }
        __syncthreads();
        const float a0 = redf[8], a1 = redf[9];

        const float* ctx0 = P.allctx + (size_t)b * 1024;
        const float* ctx1 = ctx0 + 512;
        float* xb = P.x2 + (size_t)b * 512;
        for (int c = tid; c < 512; c += 128)
            xb[c] = tanhf(a0 * ctx0[c] + a1 * ctx1[c]);
        __syncthreads();   // sm reuse safety before P4 GEMM
    }
    grid_bar(3, 128);

    // ---- P4: gates += x2 @ W_ih[:,512:]^T (64 tasks of 128x64) ----
    if (bid < 64) {
        gemm_async_core(P.x2, 512, P.W_ih + 512, 1024, nullptr, P.gates, 4096,
                        4096, 512, 1, 0, bid << 6, sm);
    }
    grid_bar(4, 128);

    // ---- P5: LSTM pointwise (gates + gates2 + biases) ----
    for (int idx = bid * 128 + tid; idx < 128 * 1024; idx += 128 * 128) {
        const int b = idx >> 10, k = idx & 1023;
        const float* g  = P.gates  + (size_t)b * 4096;
        const float* g2 = P.gates2 + (size_t)b * 4096;
        const float ig = g[k]        + g2[k]        + P.b_ih[k]        + P.b_hh[k];
        const float fg = g[1024 + k] + g2[1024 + k] + P.b_ih[1024 + k] + P.b_hh[1024 + k];
        const float gg = g[2048 + k] + g2[2048 + k] + P.b_ih[2048 + k] + P.b_hh[2048 + k];
        const float og = g[3072 + k] + g2[3072 + k] + P.b_ih[3072 + k] + P.b_hh[3072 + k];

        const float si = 1.f / (1.f + expf(-ig));
        const float sf = 1.f / (1.f + expf(-fg));
        const float so = 1.f / (1.f + expf(-og));
        const float cn = sf * P.c0[idx] + si * tanhf(gg);
        const float hn = so * tanhf(cn);

        P.hsc[idx] = hn;
        P.h_out[idx] = hn;
        P.c_out[idx] = cn;
    }
}

// ---------------------------------------------------------------------------
// Launch
// ---------------------------------------------------------------------------
static inline GemmGroup mkgrp(const float* A, int lda, const float* B, int ldb,
                              const float* bias, float* C, int ldc,
                              int M, int N, int K, int accum, int prevEnd)
{
    GemmGroup g;
    g.A = A; g.B = B; g.bias = bias; g.C = C;
    g.lda = lda; g.ldb = ldb; g.ldc = ldc;
    g.N = N; g.K = K; g.accum = accum;
    g.nbx = (N + 63) / 64;
    g.end = prevEnd + g.nbx * (M / 128);
    return g;
}

extern "C" void kernel_launch(void* const* d_in, const int* in_sizes, int n_in,
                              void* d_out, int out_size)
{
    (void)in_sizes; (void)n_in; (void)out_size;

    float* S = nullptr;
    cudaGetSymbolAddress((void**)&S, g_scratch);

    const float* input  = (const float*)d_in[0];
    const float* enc_v  = (const float*)d_in[1];
    const float* enc_a  = (const float*)d_in[2];
    const float* h0     = (const float*)d_in[3];
    const float* c0     = (const float*)d_in[4];
    const float* W_va1  = (const float*)d_in[5];
    const float* W_va2  = (const float*)d_in[6];
    const float* W_va3  = (const float*)d_in[7];
    const float* W_venc = (const float*)d_in[8];
    const float* W_aa1  = (const float*)d_in[9];
    const float* W_aa2  = (const float*)d_in[10];
    const float* W_aa3  = (const float*)d_in[11];
    const float* W_aenc = (const float*)d_in[12];
    const float* W_ca1  = (const float*)d_in[13];
    const float* W_ca2  = (const float*)d_in[14];
    const float* W_ca3  = (const float*)d_in[15];
    const float* W_ih   = (const float*)d_in[16];
    const float* W_hh   = (const float*)d_in[17];
    const float* b_ih   = (const float*)d_in[18];
    const float* b_hh   = (const float*)d_in[19];
    const float* W_out  = (const float*)d_in[20];
    const float* b_out  = (const float*)d_in[21];

    float* out    = (float*)d_out;
    float* logits = out;
    float* h_out  = out + 128 * 20000;
    float* c_out  = h_out + 128 * 1024;

    float* v2v    = S + OFF_V2V;
    float* v2a    = S + OFF_V2A;
    float* v1v    = S + OFF_V1V;
    float* v1a    = S + OFF_V1A;
    float* v1c    = S + OFF_V1C;
    float* ctxv   = S + OFF_CTXV;
    float* ctxa   = S + OFF_CTXA;
    float* allctx = S + OFF_ALLCTX;
    float* v2c    = S + OFF_V2C;
    float* x2     = S + OFF_X2;
    float* gates  = S + OFF_GATES;
    float* hsc    = S + OFF_H;
    float* vtmp   = S + OFF_VTMP;
    float* v2ctmp = S + OFF_V2CTMP;
    float* gates2 = S + OFF_GATES2;

    // ---- launch 1: everything that depends only on inputs (fat async core) ----
    GemmList L1; L1.n = 7;
    L1.g[0] = mkgrp(enc_a, 512,  W_aa2, 512,  nullptr, v2a,    512,  16384, 512,  512,  0, 0);
    L1.g[1] = mkgrp(enc_v, 1024, W_va2, 1024, nullptr, v2v,    512,  8192,  512,  1024, 0, L1.g[0].end);
    L1.g[2] = mkgrp(h0,    1024, W_hh,  1024, nullptr, gates,  4096, 128,   4096, 1024, 0, L1.g[1].end);
    L1.g[3] = mkgrp(input, 512,  W_ih,  1024, nullptr, gates2, 4096, 128,   4096, 512,  0, L1.g[2].end);
    L1.g[4] = mkgrp(h0,    1024, W_va1, 1024, nullptr, v1v,    512,  128,   512,  1024, 0, L1.g[3].end);
    L1.g[5] = mkgrp(h0,    1024, W_aa1, 1024, nullptr, v1a,    512,  128,   512,  1024, 0, L1.g[4].end);
    L1.g[6] = mkgrp(h0,    1024, W_ca1, 1024, nullptr, v1c,    512,  128,   512,  1024, 0, L1.g[5].end);
    gemm_async_grouped<<<L1.g[6].end, 128>>>(L1);

    // ---- launch 2: both attentions ----
    AttParams Pv{v1v, v2v, W_va3, enc_v, ctxv, 64, 512, 1024};
    AttParams Pa{v1a, v2a, W_aa3, enc_a, ctxa, 128, 512, 512};
    attend_both<<<256, 256>>>(Pv, Pa);

    // ---- launch 3: persistent fused chain ----
    ChainParams CP;
    CP.ctxv = ctxv; CP.ctxa = ctxa;
    CP.W_venc = W_venc; CP.W_aenc = W_aenc; CP.W_ca2 = W_ca2;
    CP.v1c = v1c; CP.W_ca3 = W_ca3; CP.W_ih = W_ih;
    CP.b_ih = b_ih; CP.b_hh = b_hh; CP.c0 = c0;
    CP.allctx = allctx; CP.vtmp = vtmp; CP.v2c = v2c; CP.v2ctmp = v2ctmp;
    CP.x2 = x2; CP.gates = gates; CP.gates2 = gates2;
    CP.hsc = hsc; CP.h_out = h_out; CP.c_out = c_out;
    fused_chain<<<128, 128>>>(CP);

    // ---- launch 4: logits on the fat async core ----
    GemmList L5; L5.n = 1;
    L5.g[0] = mkgrp(hsc, 1024, W_out, 1024, b_out, logits, 20000, 128, 20000, 1024, 0, 0);
    gemm_async_grouped<<<L5.g[0].end, 128>>>(L5);
}